// round 1
// baseline (speedup 1.0000x reference)
#include <cuda_runtime.h>

#define DM 1024
#define NH 16
#define DK 64

// Scratch (B=2, S=2048 fixed by problem)
__device__ float g_qkv[(size_t)2 * 2048 * 3 * 1024];
__device__ float g_ctx[(size_t)2 * 2048 * 1024];

// ---------------------------------------------------------------------------
// SGEMM: C[M,N] = A[M,K] @ B[K,N] + bias[N]
// 128x128 block tile, BK=8, 256 threads, 8x8 register tile per thread.
// ---------------------------------------------------------------------------
__global__ __launch_bounds__(256)
void sgemm_bias_kernel(const float* __restrict__ A, const float* __restrict__ B,
                       const float* __restrict__ bias, float* __restrict__ C,
                       int M, int N, int K)
{
    const int BM = 128, BN = 128, BK = 8;
    __shared__ float As[BK][BM];   // transposed A tile
    __shared__ float Bs[BK][BN];

    int tid = threadIdx.x;
    int tx = tid & 15;
    int ty = tid >> 4;
    int rowBase = blockIdx.y * BM;
    int colBase = blockIdx.x * BN;

    int aRow = tid >> 1;           // 0..127
    int aCol = (tid & 1) * 4;      // 0 or 4
    int bRow = tid >> 5;           // 0..7
    int bCol = (tid & 31) * 4;     // 0..124

    const float* Aptr = A + (size_t)(rowBase + aRow) * K + aCol;
    const float* Bptr = B + (size_t)bRow * N + colBase + bCol;

    float acc[8][8];
    #pragma unroll
    for (int i = 0; i < 8; i++)
        #pragma unroll
        for (int j = 0; j < 8; j++)
            acc[i][j] = 0.0f;

    for (int k0 = 0; k0 < K; k0 += BK) {
        float4 av = *(const float4*)(Aptr + k0);
        As[aCol + 0][aRow] = av.x;
        As[aCol + 1][aRow] = av.y;
        As[aCol + 2][aRow] = av.z;
        As[aCol + 3][aRow] = av.w;
        *(float4*)&Bs[bRow][bCol] = *(const float4*)(Bptr + (size_t)k0 * N);
        __syncthreads();

        #pragma unroll
        for (int kk = 0; kk < BK; kk++) {
            float4 a0 = *(const float4*)&As[kk][ty * 8];
            float4 a1 = *(const float4*)&As[kk][ty * 8 + 4];
            float4 b0 = *(const float4*)&Bs[kk][tx * 8];
            float4 b1 = *(const float4*)&Bs[kk][tx * 8 + 4];
            float a[8] = {a0.x, a0.y, a0.z, a0.w, a1.x, a1.y, a1.z, a1.w};
            float b[8] = {b0.x, b0.y, b0.z, b0.w, b1.x, b1.y, b1.z, b1.w};
            #pragma unroll
            for (int i = 0; i < 8; i++)
                #pragma unroll
                for (int j = 0; j < 8; j++)
                    acc[i][j] = fmaf(a[i], b[j], acc[i][j]);
        }
        __syncthreads();
    }

    #pragma unroll
    for (int i = 0; i < 8; i++) {
        int row = rowBase + ty * 8 + i;
        #pragma unroll
        for (int j = 0; j < 8; j += 4) {
            int col = colBase + tx * 8 + j;
            float4 o;
            o.x = acc[i][j + 0] + bias[col + 0];
            o.y = acc[i][j + 1] + bias[col + 1];
            o.z = acc[i][j + 2] + bias[col + 2];
            o.w = acc[i][j + 3] + bias[col + 3];
            *(float4*)&C[(size_t)row * N + col] = o;
        }
    }
}

// ---------------------------------------------------------------------------
// Fused flash attention (fp32, exact softmax semantics incl. mask = -1e9)
// One CTA = one (batch, head, 64-row Q tile). 256 threads, 4x4 per thread.
// qkv layout: [B*S, 3*DM]; Q at col h*64, K at 1024+h*64, V at 2048+h*64.
// ctx layout: [B*S, DM].
// ---------------------------------------------------------------------------
__global__ __launch_bounds__(256)
void attn_kernel(const float* __restrict__ qkv, const int* __restrict__ mask,
                 float* __restrict__ ctx, int S)
{
    __shared__ float QsT[64 * 64];  // [d][q]
    __shared__ float KV[64 * 64];   // K phase: [d][k]; V phase: [k][d]
    __shared__ float PsT[64 * 64];  // [k][q]

    int tid = threadIdx.x;
    int tx = tid & 15;
    int ty = tid >> 4;
    int b = blockIdx.z, h = blockIdx.y;
    int q0 = blockIdx.x * 64;
    const int ld = 3 * DM;
    const float scale = 0.125f;  // 1/sqrt(64)

    const float* Qg = qkv + (size_t)b * S * ld + h * DK;
    const float* Kg = Qg + DM;
    const float* Vg = Qg + 2 * DM;
    const int* Mg = mask + (size_t)b * S * S;

    // Load Q tile transposed: QsT[d][q]
    #pragma unroll
    for (int i = 0; i < 4; i++) {
        int idx = tid + 256 * i;
        int row = idx >> 4;
        int c4 = (idx & 15) << 2;
        float4 v = *(const float4*)&Qg[(size_t)(q0 + row) * ld + c4];
        QsT[(c4 + 0) * 64 + row] = v.x;
        QsT[(c4 + 1) * 64 + row] = v.y;
        QsT[(c4 + 2) * 64 + row] = v.z;
        QsT[(c4 + 3) * 64 + row] = v.w;
    }

    float m_i[4], l_i[4], o[4][4];
    #pragma unroll
    for (int i = 0; i < 4; i++) {
        m_i[i] = -1e30f;
        l_i[i] = 0.0f;
        #pragma unroll
        for (int j = 0; j < 4; j++) o[i][j] = 0.0f;
    }

    for (int k0 = 0; k0 < S; k0 += 64) {
        // Load K tile transposed: KV[d][k]
        #pragma unroll
        for (int i = 0; i < 4; i++) {
            int idx = tid + 256 * i;
            int row = idx >> 4;
            int c4 = (idx & 15) << 2;
            float4 v = *(const float4*)&Kg[(size_t)(k0 + row) * ld + c4];
            KV[(c4 + 0) * 64 + row] = v.x;
            KV[(c4 + 1) * 64 + row] = v.y;
            KV[(c4 + 2) * 64 + row] = v.z;
            KV[(c4 + 3) * 64 + row] = v.w;
        }
        __syncthreads();

        // S = Q K^T
        float s[4][4];
        #pragma unroll
        for (int i = 0; i < 4; i++)
            #pragma unroll
            for (int j = 0; j < 4; j++) s[i][j] = 0.0f;

        #pragma unroll 16
        for (int d = 0; d < 64; d++) {
            float4 a = *(const float4*)&QsT[d * 64 + ty * 4];
            float4 bb = *(const float4*)&KV[d * 64 + tx * 4];
            float av[4] = {a.x, a.y, a.z, a.w};
            float bv[4] = {bb.x, bb.y, bb.z, bb.w};
            #pragma unroll
            for (int i = 0; i < 4; i++)
                #pragma unroll
                for (int j = 0; j < 4; j++)
                    s[i][j] = fmaf(av[i], bv[j], s[i][j]);
        }

        // scale + mask (reference: scores scaled, then masked to -1e9)
        #pragma unroll
        for (int i = 0; i < 4; i++) {
            const int* mrow = Mg + (size_t)(q0 + ty * 4 + i) * S + k0 + tx * 4;
            int4 mv = *(const int4*)mrow;
            s[i][0] = (mv.x == 0) ? -1e9f : s[i][0] * scale;
            s[i][1] = (mv.y == 0) ? -1e9f : s[i][1] * scale;
            s[i][2] = (mv.z == 0) ? -1e9f : s[i][2] * scale;
            s[i][3] = (mv.w == 0) ? -1e9f : s[i][3] * scale;
        }

        // online softmax: row reductions across 16 tx-lanes (width 16 shuffles)
        float rmax[4], rsum[4], alpha[4];
        #pragma unroll
        for (int i = 0; i < 4; i++) {
            rmax[i] = fmaxf(fmaxf(s[i][0], s[i][1]), fmaxf(s[i][2], s[i][3]));
        }
        #pragma unroll
        for (int off = 8; off > 0; off >>= 1)
            #pragma unroll
            for (int i = 0; i < 4; i++)
                rmax[i] = fmaxf(rmax[i], __shfl_xor_sync(0xffffffffu, rmax[i], off, 16));

        #pragma unroll
        for (int i = 0; i < 4; i++) {
            float mn = fmaxf(m_i[i], rmax[i]);
            alpha[i] = __expf(m_i[i] - mn);
            m_i[i] = mn;
            rsum[i] = 0.0f;
        }
        #pragma unroll
        for (int i = 0; i < 4; i++)
            #pragma unroll
            for (int j = 0; j < 4; j++) {
                float p = __expf(s[i][j] - m_i[i]);
                s[i][j] = p;
                rsum[i] += p;
            }
        #pragma unroll
        for (int off = 8; off > 0; off >>= 1)
            #pragma unroll
            for (int i = 0; i < 4; i++)
                rsum[i] += __shfl_xor_sync(0xffffffffu, rsum[i], off, 16);

        #pragma unroll
        for (int i = 0; i < 4; i++) {
            l_i[i] = l_i[i] * alpha[i] + rsum[i];
            #pragma unroll
            for (int j = 0; j < 4; j++) o[i][j] *= alpha[i];
        }

        // store P transposed: PsT[k][q]
        #pragma unroll
        for (int i = 0; i < 4; i++)
            #pragma unroll
            for (int j = 0; j < 4; j++)
                PsT[(tx * 4 + j) * 64 + (ty * 4 + i)] = s[i][j];

        __syncthreads();  // K reads + P writes complete

        // Load V tile row-major into KV: KV[k][d]
        #pragma unroll
        for (int i = 0; i < 4; i++) {
            int idx = tid + 256 * i;
            int row = idx >> 4;
            int c4 = (idx & 15) << 2;
            *(float4*)&KV[row * 64 + c4] =
                *(const float4*)&Vg[(size_t)(k0 + row) * ld + c4];
        }
        __syncthreads();  // V + P visible

        // O += P V
        #pragma unroll 16
        for (int k = 0; k < 64; k++) {
            float4 a = *(const float4*)&PsT[k * 64 + ty * 4];
            float4 vv = *(const float4*)&KV[k * 64 + tx * 4];
            float av[4] = {a.x, a.y, a.z, a.w};
            float bv[4] = {vv.x, vv.y, vv.z, vv.w};
            #pragma unroll
            for (int i = 0; i < 4; i++)
                #pragma unroll
                for (int j = 0; j < 4; j++)
                    o[i][j] = fmaf(av[i], bv[j], o[i][j]);
        }
        __syncthreads();  // done with KV/PsT before next tile
    }

    // epilogue: normalize and write ctx[(b*S + q), h*64 + d]
    #pragma unroll
    for (int i = 0; i < 4; i++) {
        float inv = 1.0f / l_i[i];
        int q = q0 + ty * 4 + i;
        float4 ov;
        ov.x = o[i][0] * inv;
        ov.y = o[i][1] * inv;
        ov.z = o[i][2] * inv;
        ov.w = o[i][3] * inv;
        *(float4*)&ctx[(size_t)(b * S + q) * DM + h * DK + tx * 4] = ov;
    }
}

// ---------------------------------------------------------------------------
// Launch
// ---------------------------------------------------------------------------
extern "C" void kernel_launch(void* const* d_in, const int* in_sizes, int n_in,
                              void* d_out, int out_size)
{
    const float* query = (const float*)d_in[0];
    const int*   mask  = (const int*)d_in[1];
    const float* Wqkv  = (const float*)d_in[2];
    const float* bqkv  = (const float*)d_in[3];
    const float* Wout  = (const float*)d_in[4];
    const float* bout  = (const float*)d_in[5];
    float* out = (float*)d_out;

    long long qe = in_sizes[0];           // B*S*DM
    long long me = in_sizes[1];           // B*S*S
    int S = (int)((me * DM) / qe);
    int B = (int)(qe / ((long long)S * DM));
    int M = B * S;

    float* qkv = nullptr;
    float* ctx = nullptr;
    cudaGetSymbolAddress((void**)&qkv, g_qkv);
    cudaGetSymbolAddress((void**)&ctx, g_ctx);

    // 1) QKV projection: [M, DM] @ [DM, 3*DM] + b
    {
        dim3 grid((3 * DM) / 128, M / 128);
        sgemm_bias_kernel<<<grid, 256>>>(query, Wqkv, bqkv, qkv, M, 3 * DM, DM);
    }

    // 2) fused attention
    {
        dim3 grid(S / 64, NH, B);
        attn_kernel<<<grid, 256>>>(qkv, mask, ctx, S);
    }

    // 3) output projection: [M, DM] @ [DM, DM] + b
    {
        dim3 grid(DM / 128, M / 128);
        sgemm_bias_kernel<<<grid, 256>>>(ctx, Wout, bout, out, M, DM, DM);
    }
}

// round 3
// speedup vs baseline: 1.3238x; 1.3238x over previous
#include <cuda_runtime.h>
#include <cuda_bf16.h>
#include <cstdint>

#define DM 1024
#define NH 16
#define DK 64

// ---------------------------------------------------------------------------
// Scratch (B=2, S=2048 fixed => M = 4096)
// ---------------------------------------------------------------------------
__device__ float g_qkv[(size_t)4096 * 3072];          // QKV activations fp32
__device__ float g_ctx[(size_t)4096 * 1024];          // attention output fp32
__device__ __nv_bfloat16 g_ahi[(size_t)4096 * 1024];  // A split hi
__device__ __nv_bfloat16 g_alo[(size_t)4096 * 1024];  // A split lo
__device__ __nv_bfloat16 g_whi[(size_t)1024 * 3072];  // W split hi ([K,N], row-major)
__device__ __nv_bfloat16 g_wlo[(size_t)1024 * 3072];  // W split lo

__device__ __forceinline__ uint32_t smem_u32(const void* p) {
    uint32_t a;
    asm("{ .reg .u64 t; cvta.to.shared.u64 t, %1; cvt.u32.u64 %0, t; }"
        : "=r"(a) : "l"(p));
    return a;
}

// ---------------------------------------------------------------------------
// mma.sync / ldmatrix wrappers (baseline sm_103 ISA — no tcgen05)
// ---------------------------------------------------------------------------
__device__ __forceinline__ void ldm_x4(uint32_t* r, uint32_t addr) {
    asm volatile("ldmatrix.sync.aligned.m8n8.x4.shared.b16 {%0,%1,%2,%3}, [%4];"
                 : "=r"(r[0]), "=r"(r[1]), "=r"(r[2]), "=r"(r[3]) : "r"(addr));
}
__device__ __forceinline__ void ldm_x4_trans(uint32_t* r, uint32_t addr) {
    asm volatile("ldmatrix.sync.aligned.m8n8.x4.trans.shared.b16 {%0,%1,%2,%3}, [%4];"
                 : "=r"(r[0]), "=r"(r[1]), "=r"(r[2]), "=r"(r[3]) : "r"(addr));
}
__device__ __forceinline__ void mma_bf16(float* d, const uint32_t* a,
                                         uint32_t b0, uint32_t b1) {
    asm volatile(
        "mma.sync.aligned.m16n8k16.row.col.f32.bf16.bf16.f32 "
        "{%0,%1,%2,%3}, {%4,%5,%6,%7}, {%8,%9}, {%0,%1,%2,%3};"
        : "+f"(d[0]), "+f"(d[1]), "+f"(d[2]), "+f"(d[3])
        : "r"(a[0]), "r"(a[1]), "r"(a[2]), "r"(a[3]), "r"(b0), "r"(b1));
}

// ---------------------------------------------------------------------------
// Split fp32 -> bf16 hi/lo (elementwise; works for activations and W)
// ---------------------------------------------------------------------------
__global__ __launch_bounds__(256)
void split_bf16_kernel(const float* __restrict__ in, __nv_bfloat16* __restrict__ hi,
                       __nv_bfloat16* __restrict__ lo, int n4)
{
    int i = blockIdx.x * blockDim.x + threadIdx.x;
    if (i >= n4) return;
    float4 v = ((const float4*)in)[i];
    float vv[4] = {v.x, v.y, v.z, v.w};
    __nv_bfloat16 h[4], l[4];
    #pragma unroll
    for (int j = 0; j < 4; j++) {
        h[j] = __float2bfloat16(vv[j]);
        l[j] = __float2bfloat16(vv[j] - __bfloat162float(h[j]));
    }
    __nv_bfloat162* h2 = (__nv_bfloat162*)(hi + 4 * (size_t)i);
    __nv_bfloat162* l2 = (__nv_bfloat162*)(lo + 4 * (size_t)i);
    h2[0] = __nv_bfloat162(h[0], h[1]);
    h2[1] = __nv_bfloat162(h[2], h[3]);
    l2[0] = __nv_bfloat162(l[0], l[1]);
    l2[1] = __nv_bfloat162(l[2], l[3]);
}

// ---------------------------------------------------------------------------
// HMMA bf16x3 GEMM: C[M,N] = A[M,K] @ W[K,N] + bias[N]
// A hi/lo: [M,K] bf16 row-major. W hi/lo: [K,N] bf16 row-major.
// CTA 128x128, BK=32, 8 warps (warp tile 32x64), reg-prefetch double buffer.
// ---------------------------------------------------------------------------
#define A_PITCH 40   // bf16 units (80 B rows -> conflict-free ldmatrix)
#define B_PITCH 136  // bf16 units (272 B rows -> conflict-free ldmatrix.trans)
#define OFF_AH 0
#define OFF_AL 10240
#define OFF_BH 20480
#define OFF_BL 29184
#define STAGE_BYTES 37888

__global__ __launch_bounds__(256, 1)
void gemm_hmma_kernel(const __nv_bfloat16* __restrict__ Ah,
                      const __nv_bfloat16* __restrict__ Al,
                      const __nv_bfloat16* __restrict__ Wh,
                      const __nv_bfloat16* __restrict__ Wl,
                      const float* __restrict__ bias, float* __restrict__ C,
                      int M, int N, int K)
{
    extern __shared__ char dsm[];
    const uint32_t sbase = smem_u32(dsm);

    const int tid = threadIdx.x;
    const int lane = tid & 31;
    const int wid = tid >> 5;
    const int wm = (wid & 3) * 32;   // warp m offset in tile
    const int wn = (wid >> 2) * 64;  // warp n offset in tile
    const int m0 = blockIdx.y * 128;
    const int n0 = blockIdx.x * 128;

    // ldmatrix per-lane byte offsets
    const uint32_t aOff = (uint32_t)(wm + (lane & 15)) * (A_PITCH * 2)
                        + (uint32_t)((lane >> 4) << 4);           // +16B for k+8 half
    const int brow = (lane & 7) + (lane & 8);
    const uint32_t bOff = (uint32_t)brow * (B_PITCH * 2)
                        + (uint32_t)(((lane & 16) >> 1) << 1);    // +16B (8 cols * 2B)

    // gmem chunk assignment (2 x 16B per tile per thread)
    const int chA0 = tid, chA1 = tid + 256;          // 512 chunks: row=ch>>2, col16=ch&3
    const int chB0 = tid, chB1 = tid + 256;          // 512 chunks: row=ch>>4, col16=ch&15

    float acc[2][8][4];
    #pragma unroll
    for (int mi = 0; mi < 2; mi++)
        #pragma unroll
        for (int nj = 0; nj < 8; nj++)
            #pragma unroll
            for (int q = 0; q < 4; q++) acc[mi][nj][q] = 0.0f;

    const int nStages = K >> 5;

    // ---- prologue: stage 0 -> buf 0 ----
    {
        const int k0 = 0;
        #pragma unroll
        for (int i = 0; i < 2; i++) {
            int ch = (i == 0) ? chA0 : chA1;
            int r = ch >> 2, c = (ch & 3) << 3;
            uint4 vh = *(const uint4*)(Ah + (size_t)(m0 + r) * K + k0 + c);
            uint4 vl = *(const uint4*)(Al + (size_t)(m0 + r) * K + k0 + c);
            *(uint4*)(dsm + OFF_AH + r * (A_PITCH * 2) + c * 2) = vh;
            *(uint4*)(dsm + OFF_AL + r * (A_PITCH * 2) + c * 2) = vl;
            int chb = (i == 0) ? chB0 : chB1;
            int rb = chb >> 4, cb = (chb & 15) << 3;
            uint4 wh = *(const uint4*)(Wh + (size_t)(k0 + rb) * N + n0 + cb);
            uint4 wl = *(const uint4*)(Wl + (size_t)(k0 + rb) * N + n0 + cb);
            *(uint4*)(dsm + OFF_BH + rb * (B_PITCH * 2) + cb * 2) = wh;
            *(uint4*)(dsm + OFF_BL + rb * (B_PITCH * 2) + cb * 2) = wl;
        }
    }
    __syncthreads();

    for (int s = 0; s < nStages; s++) {
        const int buf = s & 1;
        const uint32_t sb = sbase + (uint32_t)buf * STAGE_BYTES;
        const bool hasNext = (s + 1) < nStages;

        // prefetch next stage into registers
        uint4 pAh[2], pAl[2], pBh[2], pBl[2];
        if (hasNext) {
            const int k0 = (s + 1) << 5;
            #pragma unroll
            for (int i = 0; i < 2; i++) {
                int ch = (i == 0) ? chA0 : chA1;
                int r = ch >> 2, c = (ch & 3) << 3;
                pAh[i] = *(const uint4*)(Ah + (size_t)(m0 + r) * K + k0 + c);
                pAl[i] = *(const uint4*)(Al + (size_t)(m0 + r) * K + k0 + c);
                int chb = (i == 0) ? chB0 : chB1;
                int rb = chb >> 4, cb = (chb & 15) << 3;
                pBh[i] = *(const uint4*)(Wh + (size_t)(k0 + rb) * N + n0 + cb);
                pBl[i] = *(const uint4*)(Wl + (size_t)(k0 + rb) * N + n0 + cb);
            }
        }

        // ---- compute stage s ----
        #pragma unroll
        for (int k16 = 0; k16 < 2; k16++) {
            uint32_t afh[2][4], afl[2][4];
            #pragma unroll
            for (int mi = 0; mi < 2; mi++) {
                uint32_t aa = sb + aOff + (uint32_t)mi * (16 * A_PITCH * 2)
                            + (uint32_t)k16 * 32;  // 16 bf16 = 32B per k-step
                ldm_x4(afh[mi], aa + OFF_AH);
                ldm_x4(afl[mi], aa + OFF_AL);
            }
            #pragma unroll
            for (int t = 0; t < 4; t++) {
                uint32_t bfh[4], bfl[4];
                uint32_t ba = sb + bOff + (uint32_t)k16 * (16 * B_PITCH * 2)
                            + (uint32_t)(wn + t * 16) * 2;
                ldm_x4_trans(bfh, ba + OFF_BH);
                ldm_x4_trans(bfl, ba + OFF_BL);
                #pragma unroll
                for (int half = 0; half < 2; half++) {
                    int nj = t * 2 + half;
                    uint32_t b0 = bfh[half * 2], b1 = bfh[half * 2 + 1];
                    uint32_t l0 = bfl[half * 2], l1 = bfl[half * 2 + 1];
                    #pragma unroll
                    for (int mi = 0; mi < 2; mi++) {
                        mma_bf16(acc[mi][nj], afh[mi], b0, b1);
                        mma_bf16(acc[mi][nj], afl[mi], b0, b1);
                        mma_bf16(acc[mi][nj], afh[mi], l0, l1);
                    }
                }
            }
        }

        // store prefetched stage into other buffer
        if (hasNext) {
            char* db = dsm + ((s + 1) & 1) * STAGE_BYTES;
            #pragma unroll
            for (int i = 0; i < 2; i++) {
                int ch = (i == 0) ? chA0 : chA1;
                int r = ch >> 2, c = (ch & 3) << 3;
                *(uint4*)(db + OFF_AH + r * (A_PITCH * 2) + c * 2) = pAh[i];
                *(uint4*)(db + OFF_AL + r * (A_PITCH * 2) + c * 2) = pAl[i];
                int chb = (i == 0) ? chB0 : chB1;
                int rb = chb >> 4, cb = (chb & 15) << 3;
                *(uint4*)(db + OFF_BH + rb * (B_PITCH * 2) + cb * 2) = pBh[i];
                *(uint4*)(db + OFF_BL + rb * (B_PITCH * 2) + cb * 2) = pBl[i];
            }
        }
        __syncthreads();
    }

    // ---- epilogue: bias + store ----
    #pragma unroll
    for (int mi = 0; mi < 2; mi++) {
        int r0 = m0 + wm + mi * 16 + (lane >> 2);
        #pragma unroll
        for (int nj = 0; nj < 8; nj++) {
            int c = n0 + wn + nj * 8 + ((lane & 3) << 1);
            float2 bv = *(const float2*)&bias[c];
            float2 o0, o1;
            o0.x = acc[mi][nj][0] + bv.x;
            o0.y = acc[mi][nj][1] + bv.y;
            o1.x = acc[mi][nj][2] + bv.x;
            o1.y = acc[mi][nj][3] + bv.y;
            *(float2*)&C[(size_t)r0 * N + c] = o0;
            *(float2*)&C[(size_t)(r0 + 8) * N + c] = o1;
        }
    }
}

// ---------------------------------------------------------------------------
// Fused flash attention (unchanged — fp32 CUDA cores)
// ---------------------------------------------------------------------------
__global__ __launch_bounds__(256)
void attn_kernel(const float* __restrict__ qkv, const int* __restrict__ mask,
                 float* __restrict__ ctx, int S)
{
    __shared__ float QsT[64 * 64];
    __shared__ float KV[64 * 64];
    __shared__ float PsT[64 * 64];

    int tid = threadIdx.x;
    int tx = tid & 15;
    int ty = tid >> 4;
    int b = blockIdx.z, h = blockIdx.y;
    int q0 = blockIdx.x * 64;
    const int ld = 3 * DM;
    const float scale = 0.125f;

    const float* Qg = qkv + (size_t)b * S * ld + h * DK;
    const float* Kg = Qg + DM;
    const float* Vg = Qg + 2 * DM;
    const int* Mg = mask + (size_t)b * S * S;

    #pragma unroll
    for (int i = 0; i < 4; i++) {
        int idx = tid + 256 * i;
        int row = idx >> 4;
        int c4 = (idx & 15) << 2;
        float4 v = *(const float4*)&Qg[(size_t)(q0 + row) * ld + c4];
        QsT[(c4 + 0) * 64 + row] = v.x;
        QsT[(c4 + 1) * 64 + row] = v.y;
        QsT[(c4 + 2) * 64 + row] = v.z;
        QsT[(c4 + 3) * 64 + row] = v.w;
    }

    float m_i[4], l_i[4], o[4][4];
    #pragma unroll
    for (int i = 0; i < 4; i++) {
        m_i[i] = -1e30f;
        l_i[i] = 0.0f;
        #pragma unroll
        for (int j = 0; j < 4; j++) o[i][j] = 0.0f;
    }

    for (int k0 = 0; k0 < S; k0 += 64) {
        #pragma unroll
        for (int i = 0; i < 4; i++) {
            int idx = tid + 256 * i;
            int row = idx >> 4;
            int c4 = (idx & 15) << 2;
            float4 v = *(const float4*)&Kg[(size_t)(k0 + row) * ld + c4];
            KV[(c4 + 0) * 64 + row] = v.x;
            KV[(c4 + 1) * 64 + row] = v.y;
            KV[(c4 + 2) * 64 + row] = v.z;
            KV[(c4 + 3) * 64 + row] = v.w;
        }
        __syncthreads();

        float s[4][4];
        #pragma unroll
        for (int i = 0; i < 4; i++)
            #pragma unroll
            for (int j = 0; j < 4; j++) s[i][j] = 0.0f;

        #pragma unroll 16
        for (int d = 0; d < 64; d++) {
            float4 a = *(const float4*)&QsT[d * 64 + ty * 4];
            float4 bb = *(const float4*)&KV[d * 64 + tx * 4];
            float av[4] = {a.x, a.y, a.z, a.w};
            float bv[4] = {bb.x, bb.y, bb.z, bb.w};
            #pragma unroll
            for (int i = 0; i < 4; i++)
                #pragma unroll
                for (int j = 0; j < 4; j++)
                    s[i][j] = fmaf(av[i], bv[j], s[i][j]);
        }

        #pragma unroll
        for (int i = 0; i < 4; i++) {
            const int* mrow = Mg + (size_t)(q0 + ty * 4 + i) * S + k0 + tx * 4;
            int4 mv = *(const int4*)mrow;
            s[i][0] = (mv.x == 0) ? -1e9f : s[i][0] * scale;
            s[i][1] = (mv.y == 0) ? -1e9f : s[i][1] * scale;
            s[i][2] = (mv.z == 0) ? -1e9f : s[i][2] * scale;
            s[i][3] = (mv.w == 0) ? -1e9f : s[i][3] * scale;
        }

        float rmax[4], rsum[4], alpha[4];
        #pragma unroll
        for (int i = 0; i < 4; i++)
            rmax[i] = fmaxf(fmaxf(s[i][0], s[i][1]), fmaxf(s[i][2], s[i][3]));
        #pragma unroll
        for (int off = 8; off > 0; off >>= 1)
            #pragma unroll
            for (int i = 0; i < 4; i++)
                rmax[i] = fmaxf(rmax[i], __shfl_xor_sync(0xffffffffu, rmax[i], off, 16));

        #pragma unroll
        for (int i = 0; i < 4; i++) {
            float mn = fmaxf(m_i[i], rmax[i]);
            alpha[i] = __expf(m_i[i] - mn);
            m_i[i] = mn;
            rsum[i] = 0.0f;
        }
        #pragma unroll
        for (int i = 0; i < 4; i++)
            #pragma unroll
            for (int j = 0; j < 4; j++) {
                float p = __expf(s[i][j] - m_i[i]);
                s[i][j] = p;
                rsum[i] += p;
            }
        #pragma unroll
        for (int off = 8; off > 0; off >>= 1)
            #pragma unroll
            for (int i = 0; i < 4; i++)
                rsum[i] += __shfl_xor_sync(0xffffffffu, rsum[i], off, 16);

        #pragma unroll
        for (int i = 0; i < 4; i++) {
            l_i[i] = l_i[i] * alpha[i] + rsum[i];
            #pragma unroll
            for (int j = 0; j < 4; j++) o[i][j] *= alpha[i];
        }

        #pragma unroll
        for (int i = 0; i < 4; i++)
            #pragma unroll
            for (int j = 0; j < 4; j++)
                PsT[(tx * 4 + j) * 64 + (ty * 4 + i)] = s[i][j];

        __syncthreads();

        #pragma unroll
        for (int i = 0; i < 4; i++) {
            int idx = tid + 256 * i;
            int row = idx >> 4;
            int c4 = (idx & 15) << 2;
            *(float4*)&KV[row * 64 + c4] =
                *(const float4*)&Vg[(size_t)(k0 + row) * ld + c4];
        }
        __syncthreads();

        #pragma unroll 16
        for (int k = 0; k < 64; k++) {
            float4 a = *(const float4*)&PsT[k * 64 + ty * 4];
            float4 vv = *(const float4*)&KV[k * 64 + tx * 4];
            float av[4] = {a.x, a.y, a.z, a.w};
            float bv[4] = {vv.x, vv.y, vv.z, vv.w};
            #pragma unroll
            for (int i = 0; i < 4; i++)
                #pragma unroll
                for (int j = 0; j < 4; j++)
                    o[i][j] = fmaf(av[i], bv[j], o[i][j]);
        }
        __syncthreads();
    }

    #pragma unroll
    for (int i = 0; i < 4; i++) {
        float inv = 1.0f / l_i[i];
        int q = q0 + ty * 4 + i;
        float4 ov;
        ov.x = o[i][0] * inv;
        ov.y = o[i][1] * inv;
        ov.z = o[i][2] * inv;
        ov.w = o[i][3] * inv;
        *(float4*)&ctx[(size_t)(b * S + q) * DM + h * DK + tx * 4] = ov;
    }
}

// ---------------------------------------------------------------------------
// Launch
// ---------------------------------------------------------------------------
extern "C" void kernel_launch(void* const* d_in, const int* in_sizes, int n_in,
                              void* d_out, int out_size)
{
    const float* query = (const float*)d_in[0];
    const int*   mask  = (const int*)d_in[1];
    const float* Wqkv  = (const float*)d_in[2];
    const float* bqkv  = (const float*)d_in[3];
    const float* Wout  = (const float*)d_in[4];
    const float* bout  = (const float*)d_in[5];
    float* out = (float*)d_out;

    long long qe = in_sizes[0];
    long long me = in_sizes[1];
    int S = (int)((me * DM) / qe);
    int B = (int)(qe / ((long long)S * DM));
    int M = B * S;

    float *qkv, *ctx;
    __nv_bfloat16 *ahi, *alo, *whi, *wlo;
    cudaGetSymbolAddress((void**)&qkv, g_qkv);
    cudaGetSymbolAddress((void**)&ctx, g_ctx);
    cudaGetSymbolAddress((void**)&ahi, g_ahi);
    cudaGetSymbolAddress((void**)&alo, g_alo);
    cudaGetSymbolAddress((void**)&whi, g_whi);
    cudaGetSymbolAddress((void**)&wlo, g_wlo);

    const int GEMM_SMEM = 2 * STAGE_BYTES;
    cudaFuncSetAttribute(gemm_hmma_kernel,
                         cudaFuncAttributeMaxDynamicSharedMemorySize, GEMM_SMEM);

    // 1) split W_qkv (elementwise, keeps [K,N] layout)
    {
        int n4 = (DM * 3 * DM) / 4;
        split_bf16_kernel<<<(n4 + 255) / 256, 256>>>(Wqkv, whi, wlo, n4);
    }
    // 2) split query
    {
        int n4 = (M * DM) / 4;
        split_bf16_kernel<<<(n4 + 255) / 256, 256>>>(query, ahi, alo, n4);
    }
    // 3) QKV GEMM: [M, DM] x [DM, 3DM]
    {
        dim3 grid((3 * DM) / 128, M / 128);
        gemm_hmma_kernel<<<grid, 256, GEMM_SMEM>>>(ahi, alo, whi, wlo, bqkv, qkv,
                                                   M, 3 * DM, DM);
    }
    // 4) attention
    {
        dim3 grid(S / 64, NH, B);
        attn_kernel<<<grid, 256>>>(qkv, mask, ctx, S);
    }
    // 5) split ctx
    {
        int n4 = (M * DM) / 4;
        split_bf16_kernel<<<(n4 + 255) / 256, 256>>>(ctx, ahi, alo, n4);
    }
    // 6) split W_out
    {
        int n4 = (DM * DM) / 4;
        split_bf16_kernel<<<(n4 + 255) / 256, 256>>>(Wout, whi, wlo, n4);
    }
    // 7) out GEMM: [M, DM] x [DM, DM]
    {
        dim3 grid(DM / 128, M / 128);
        gemm_hmma_kernel<<<grid, 256, GEMM_SMEM>>>(ahi, alo, whi, wlo, bout, out,
                                                   M, DM, DM);
    }
}

// round 4
// speedup vs baseline: 3.1040x; 2.3448x over previous
#include <cuda_runtime.h>
#include <cuda_bf16.h>
#include <cstdint>

#define DM 1024
#define NH 16
#define DK 64
#define LOG2E 1.4426950408889634f

// ---------------------------------------------------------------------------
// Scratch (B=2, S=2048 fixed => M = 4096)
// ---------------------------------------------------------------------------
__device__ __nv_bfloat16 g_qkvh[(size_t)4096 * 3072]; // QKV hi
__device__ __nv_bfloat16 g_qkvl[(size_t)4096 * 3072]; // QKV lo
__device__ __nv_bfloat16 g_ahi[(size_t)4096 * 1024];  // A / ctx hi
__device__ __nv_bfloat16 g_alo[(size_t)4096 * 1024];  // A / ctx lo
__device__ __nv_bfloat16 g_whi[(size_t)1024 * 3072];  // W hi ([K,N] row-major)
__device__ __nv_bfloat16 g_wlo[(size_t)1024 * 3072];  // W lo
__device__ uint32_t g_bm[(size_t)2 * 2048 * 64];      // mask bitmask

__device__ __forceinline__ uint32_t smem_u32(const void* p) {
    uint32_t a;
    asm("{ .reg .u64 t; cvta.to.shared.u64 t, %1; cvt.u32.u64 %0, t; }"
        : "=r"(a) : "l"(p));
    return a;
}
__device__ __forceinline__ void ldm_x4(uint32_t* r, uint32_t addr) {
    asm volatile("ldmatrix.sync.aligned.m8n8.x4.shared.b16 {%0,%1,%2,%3}, [%4];"
                 : "=r"(r[0]), "=r"(r[1]), "=r"(r[2]), "=r"(r[3]) : "r"(addr));
}
__device__ __forceinline__ void ldm_x4_trans(uint32_t* r, uint32_t addr) {
    asm volatile("ldmatrix.sync.aligned.m8n8.x4.trans.shared.b16 {%0,%1,%2,%3}, [%4];"
                 : "=r"(r[0]), "=r"(r[1]), "=r"(r[2]), "=r"(r[3]) : "r"(addr));
}
__device__ __forceinline__ void mma_bf16(float* d, const uint32_t* a,
                                         uint32_t b0, uint32_t b1) {
    asm volatile(
        "mma.sync.aligned.m16n8k16.row.col.f32.bf16.bf16.f32 "
        "{%0,%1,%2,%3}, {%4,%5,%6,%7}, {%8,%9}, {%0,%1,%2,%3};"
        : "+f"(d[0]), "+f"(d[1]), "+f"(d[2]), "+f"(d[3])
        : "r"(a[0]), "r"(a[1]), "r"(a[2]), "r"(a[3]), "r"(b0), "r"(b1));
}
__device__ __forceinline__ float fast_ex2(float x) {
    float y;
    asm("ex2.approx.f32 %0, %1;" : "=f"(y) : "f"(x));
    return y;
}
__device__ __forceinline__ uint32_t pack2(float x, float y) {
    __nv_bfloat162 t = __floats2bfloat162_rn(x, y);
    return *reinterpret_cast<uint32_t*>(&t);
}
__device__ __forceinline__ void split2(float x, float y, uint32_t& hi, uint32_t& lo) {
    __nv_bfloat16 hx = __float2bfloat16(x), hy = __float2bfloat16(y);
    __nv_bfloat162 hp(hx, hy);
    hi = *reinterpret_cast<uint32_t*>(&hp);
    lo = pack2(x - __bfloat162float(hx), y - __bfloat162float(hy));
}
__device__ __forceinline__ void cp16(uint32_t saddr, const void* gaddr) {
    asm volatile("cp.async.cg.shared.global [%0], [%1], 16;" :: "r"(saddr), "l"(gaddr));
}

// ---------------------------------------------------------------------------
// Split fp32 -> bf16 hi/lo
// ---------------------------------------------------------------------------
__global__ __launch_bounds__(256)
void split_bf16_kernel(const float* __restrict__ in, __nv_bfloat16* __restrict__ hi,
                       __nv_bfloat16* __restrict__ lo, int n4)
{
    int i = blockIdx.x * blockDim.x + threadIdx.x;
    if (i >= n4) return;
    float4 v = ((const float4*)in)[i];
    uint32_t h0, l0, h1, l1;
    split2(v.x, v.y, h0, l0);
    split2(v.z, v.w, h1, l1);
    uint2* hp = (uint2*)(hi + 4 * (size_t)i);
    uint2* lp = (uint2*)(lo + 4 * (size_t)i);
    *hp = make_uint2(h0, h1);
    *lp = make_uint2(l0, l1);
}

// ---------------------------------------------------------------------------
// Mask int32 -> bitmask
// ---------------------------------------------------------------------------
__global__ __launch_bounds__(256)
void mask_bits_kernel(const int* __restrict__ mask, uint32_t* __restrict__ bm, int n)
{
    int i = blockIdx.x * blockDim.x + threadIdx.x;
    unsigned bit = (i < n) ? (mask[i] != 0) : 0u;
    unsigned w = __ballot_sync(0xffffffffu, bit);
    if ((i & 31) == 0 && i < n) bm[i >> 5] = w;
}

// ---------------------------------------------------------------------------
// HMMA bf16x3 GEMM: OUT=0 -> fp32 C+bias ; OUT=1 -> bf16 hi/lo (bias added)
// ---------------------------------------------------------------------------
#define A_PITCH 40
#define B_PITCH 136
#define OFF_AH 0
#define OFF_AL 10240
#define OFF_BH 20480
#define OFF_BL 29184
#define STAGE_BYTES 37888

template <int OUT>
__global__ __launch_bounds__(256, 1)
void gemm_hmma_kernel(const __nv_bfloat16* __restrict__ Ah,
                      const __nv_bfloat16* __restrict__ Al,
                      const __nv_bfloat16* __restrict__ Wh,
                      const __nv_bfloat16* __restrict__ Wl,
                      const float* __restrict__ bias, float* __restrict__ C,
                      __nv_bfloat16* __restrict__ Ch, __nv_bfloat16* __restrict__ Cl,
                      int M, int N, int K)
{
    extern __shared__ char dsm[];
    const uint32_t sbase = smem_u32(dsm);

    const int tid = threadIdx.x;
    const int lane = tid & 31;
    const int wid = tid >> 5;
    const int wm = (wid & 3) * 32;
    const int wn = (wid >> 2) * 64;
    const int m0 = blockIdx.y * 128;
    const int n0 = blockIdx.x * 128;

    const uint32_t aOff = (uint32_t)(wm + (lane & 15)) * (A_PITCH * 2)
                        + (uint32_t)((lane >> 4) << 4);
    const int brow = (lane & 7) + (lane & 8);
    const uint32_t bOff = (uint32_t)brow * (B_PITCH * 2) + (uint32_t)(lane & 16);

    const int chA0 = tid, chA1 = tid + 256;
    const int chB0 = tid, chB1 = tid + 256;

    float acc[2][8][4];
    #pragma unroll
    for (int mi = 0; mi < 2; mi++)
        #pragma unroll
        for (int nj = 0; nj < 8; nj++)
            #pragma unroll
            for (int q = 0; q < 4; q++) acc[mi][nj][q] = 0.0f;

    const int nStages = K >> 5;

    {
        #pragma unroll
        for (int i = 0; i < 2; i++) {
            int ch = (i == 0) ? chA0 : chA1;
            int r = ch >> 2, c = (ch & 3) << 3;
            *(uint4*)(dsm + OFF_AH + r * (A_PITCH * 2) + c * 2) =
                *(const uint4*)(Ah + (size_t)(m0 + r) * K + c);
            *(uint4*)(dsm + OFF_AL + r * (A_PITCH * 2) + c * 2) =
                *(const uint4*)(Al + (size_t)(m0 + r) * K + c);
            int chb = (i == 0) ? chB0 : chB1;
            int rb = chb >> 4, cb = (chb & 15) << 3;
            *(uint4*)(dsm + OFF_BH + rb * (B_PITCH * 2) + cb * 2) =
                *(const uint4*)(Wh + (size_t)rb * N + n0 + cb);
            *(uint4*)(dsm + OFF_BL + rb * (B_PITCH * 2) + cb * 2) =
                *(const uint4*)(Wl + (size_t)rb * N + n0 + cb);
        }
    }
    __syncthreads();

    for (int s = 0; s < nStages; s++) {
        const int buf = s & 1;
        const uint32_t sb = sbase + (uint32_t)buf * STAGE_BYTES;
        const bool hasNext = (s + 1) < nStages;

        uint4 pAh[2], pAl[2], pBh[2], pBl[2];
        if (hasNext) {
            const int k0 = (s + 1) << 5;
            #pragma unroll
            for (int i = 0; i < 2; i++) {
                int ch = (i == 0) ? chA0 : chA1;
                int r = ch >> 2, c = (ch & 3) << 3;
                pAh[i] = *(const uint4*)(Ah + (size_t)(m0 + r) * K + k0 + c);
                pAl[i] = *(const uint4*)(Al + (size_t)(m0 + r) * K + k0 + c);
                int chb = (i == 0) ? chB0 : chB1;
                int rb = chb >> 4, cb = (chb & 15) << 3;
                pBh[i] = *(const uint4*)(Wh + (size_t)(k0 + rb) * N + n0 + cb);
                pBl[i] = *(const uint4*)(Wl + (size_t)(k0 + rb) * N + n0 + cb);
            }
        }

        #pragma unroll
        for (int k16 = 0; k16 < 2; k16++) {
            uint32_t afh[2][4], afl[2][4];
            #pragma unroll
            for (int mi = 0; mi < 2; mi++) {
                uint32_t aa = sb + aOff + (uint32_t)mi * (16 * A_PITCH * 2)
                            + (uint32_t)k16 * 32;
                ldm_x4(afh[mi], aa + OFF_AH);
                ldm_x4(afl[mi], aa + OFF_AL);
            }
            #pragma unroll
            for (int t = 0; t < 4; t++) {
                uint32_t bfh[4], bfl[4];
                uint32_t ba = sb + bOff + (uint32_t)k16 * (16 * B_PITCH * 2)
                            + (uint32_t)(wn + t * 16) * 2;
                ldm_x4_trans(bfh, ba + OFF_BH);
                ldm_x4_trans(bfl, ba + OFF_BL);
                #pragma unroll
                for (int half = 0; half < 2; half++) {
                    int nj = t * 2 + half;
                    uint32_t b0 = bfh[half * 2], b1 = bfh[half * 2 + 1];
                    uint32_t l0 = bfl[half * 2], l1 = bfl[half * 2 + 1];
                    #pragma unroll
                    for (int mi = 0; mi < 2; mi++) {
                        mma_bf16(acc[mi][nj], afh[mi], b0, b1);
                        mma_bf16(acc[mi][nj], afl[mi], b0, b1);
                        mma_bf16(acc[mi][nj], afh[mi], l0, l1);
                    }
                }
            }
        }

        if (hasNext) {
            char* db = dsm + ((s + 1) & 1) * STAGE_BYTES;
            #pragma unroll
            for (int i = 0; i < 2; i++) {
                int ch = (i == 0) ? chA0 : chA1;
                int r = ch >> 2, c = (ch & 3) << 3;
                *(uint4*)(db + OFF_AH + r * (A_PITCH * 2) + c * 2) = pAh[i];
                *(uint4*)(db + OFF_AL + r * (A_PITCH * 2) + c * 2) = pAl[i];
                int chb = (i == 0) ? chB0 : chB1;
                int rb = chb >> 4, cb = (chb & 15) << 3;
                *(uint4*)(db + OFF_BH + rb * (B_PITCH * 2) + cb * 2) = pBh[i];
                *(uint4*)(db + OFF_BL + rb * (B_PITCH * 2) + cb * 2) = pBl[i];
            }
        }
        __syncthreads();
    }

    #pragma unroll
    for (int mi = 0; mi < 2; mi++) {
        int r0 = m0 + wm + mi * 16 + (lane >> 2);
        #pragma unroll
        for (int nj = 0; nj < 8; nj++) {
            int c = n0 + wn + nj * 8 + ((lane & 3) << 1);
            float2 bv = *(const float2*)&bias[c];
            float x0 = acc[mi][nj][0] + bv.x, y0 = acc[mi][nj][1] + bv.y;
            float x1 = acc[mi][nj][2] + bv.x, y1 = acc[mi][nj][3] + bv.y;
            if constexpr (OUT == 0) {
                *(float2*)&C[(size_t)r0 * N + c] = make_float2(x0, y0);
                *(float2*)&C[(size_t)(r0 + 8) * N + c] = make_float2(x1, y1);
            } else {
                uint32_t h, l;
                split2(x0, y0, h, l);
                *(uint32_t*)&Ch[(size_t)r0 * N + c] = h;
                *(uint32_t*)&Cl[(size_t)r0 * N + c] = l;
                split2(x1, y1, h, l);
                *(uint32_t*)&Ch[(size_t)(r0 + 8) * N + c] = h;
                *(uint32_t*)&Cl[(size_t)(r0 + 8) * N + c] = l;
            }
        }
    }
}

// ---------------------------------------------------------------------------
// HMMA flash attention (bf16 x3 split), CTA = 128 q-rows, k-tiles of 64.
// smem: QH[128x72], QL[128x72], 2 stages of {KH,KL,VH,VL}[64x72] (pitch 72 bf16)
// ---------------------------------------------------------------------------
#define AT_PITCHB 144
#define AT_QH 0
#define AT_QL 18432
#define AT_STG 36864
#define AT_STGSZ 36864
#define AT_K2L 9216
#define AT_VH 18432
#define AT_SMEM (AT_STG + 2 * AT_STGSZ)

__global__ __launch_bounds__(256, 2)
void attn_mma_kernel(const __nv_bfloat16* __restrict__ qkvh,
                     const __nv_bfloat16* __restrict__ qkvl,
                     const uint32_t* __restrict__ bm,
                     __nv_bfloat16* __restrict__ ctxh,
                     __nv_bfloat16* __restrict__ ctxl, int S)
{
    extern __shared__ char sm[];
    const uint32_t sb = smem_u32(sm);

    const int tid = threadIdx.x;
    const int lane = tid & 31;
    const int w = tid >> 5;
    const int b = blockIdx.z, h = blockIdx.y;
    const int q0 = blockIdx.x * 128;
    const int words = S >> 5;

    // Q tile load (hi/lo): 2048 16B chunks
    #pragma unroll
    for (int i = 0; i < 8; i++) {
        int c = tid + 256 * i;
        int arr = c >> 10, row = (c >> 3) & 127, ch = c & 7;
        const __nv_bfloat16* src = (arr ? qkvl : qkvh)
            + (size_t)(b * S + q0 + row) * 3072 + h * DK + ch * 8;
        *(uint4*)(sm + arr * AT_QL + row * AT_PITCHB + ch * 16) = *(const uint4*)src;
    }

    // stage loader
    auto load_stage = [&](int ktIdx, int buf) {
        const uint32_t stg = sb + AT_STG + (uint32_t)buf * AT_STGSZ;
        #pragma unroll
        for (int i = 0; i < 8; i++) {
            int c = tid + 256 * i;
            int arr = c >> 9, row = (c >> 3) & 63, ch = c & 7;
            const __nv_bfloat16* gp = ((arr & 1) ? qkvl : qkvh)
                + (size_t)(b * S + ktIdx * 64 + row) * 3072
                + ((arr >> 1) ? 2048 : 1024) + h * DK + ch * 8;
            cp16(stg + arr * AT_K2L + row * AT_PITCHB + ch * 16, gp);
        }
        asm volatile("cp.async.commit_group;");
    };

    load_stage(0, 0);

    const uint32_t qfoff = (uint32_t)(w * 16 + (lane & 15)) * AT_PITCHB
                         + (uint32_t)((lane >> 4) << 4);
    const int qg0 = q0 + w * 16 + (lane >> 2);
    const size_t bmR0 = (size_t)(b * S + qg0) * words;
    const size_t bmR1 = bmR0 + (size_t)8 * words;

    float O[8][4];
    #pragma unroll
    for (int j = 0; j < 8; j++)
        #pragma unroll
        for (int q = 0; q < 4; q++) O[j][q] = 0.0f;
    float m0r = -1e30f, m1r = -1e30f, l0r = 0.0f, l1r = 0.0f;

    const int nKT = S >> 6;
    for (int kt = 0; kt < nKT; kt++) {
        const int buf = kt & 1;
        const bool hasNext = (kt + 1) < nKT;
        if (hasNext) load_stage(kt + 1, buf ^ 1);
        if (hasNext) asm volatile("cp.async.wait_group 1;");
        else         asm volatile("cp.async.wait_group 0;");
        __syncthreads();

        const uint32_t stg = sb + AT_STG + (uint32_t)buf * AT_STGSZ;

        // ---- S = Qh Kh + Ql Kh + Qh Kl ----
        float s[8][4];
        #pragma unroll
        for (int j = 0; j < 8; j++)
            #pragma unroll
            for (int q = 0; q < 4; q++) s[j][q] = 0.0f;

        #pragma unroll
        for (int t = 0; t < 4; t++) {
            uint32_t qht[4], qlt[4];
            ldm_x4(qht, sb + AT_QH + qfoff + t * 32);
            ldm_x4(qlt, sb + AT_QL + qfoff + t * 32);
            #pragma unroll
            for (int np = 0; np < 4; np++) {
                uint32_t kh[4], kl[4];
                uint32_t ka = stg + (uint32_t)(np * 16 + (lane & 15)) * AT_PITCHB
                            + (uint32_t)((lane >> 4) << 4) + t * 32;
                ldm_x4(kh, ka);
                ldm_x4(kl, ka + AT_K2L);
                mma_bf16(s[2 * np],     qht, kh[0], kh[2]);
                mma_bf16(s[2 * np + 1], qht, kh[1], kh[3]);
                mma_bf16(s[2 * np],     qlt, kh[0], kh[2]);
                mma_bf16(s[2 * np + 1], qlt, kh[1], kh[3]);
                mma_bf16(s[2 * np],     qht, kl[0], kl[2]);
                mma_bf16(s[2 * np + 1], qht, kl[1], kl[3]);
            }
        }

        // ---- mask + online softmax ----
        uint32_t w00 = bm[bmR0 + kt * 2], w01 = bm[bmR0 + kt * 2 + 1];
        uint32_t w10 = bm[bmR1 + kt * 2], w11 = bm[bmR1 + kt * 2 + 1];
        float mx0 = -1e30f, mx1 = -1e30f;
        #pragma unroll
        for (int j = 0; j < 8; j++) {
            uint32_t wr0 = (j < 4) ? w00 : w01;
            uint32_t wr1 = (j < 4) ? w10 : w11;
            int bp = ((j & 3) * 8) + (lane & 3) * 2;
            s[j][0] = ((wr0 >> bp) & 1)       ? s[j][0] * 0.125f : -1e9f;
            s[j][1] = ((wr0 >> (bp + 1)) & 1) ? s[j][1] * 0.125f : -1e9f;
            s[j][2] = ((wr1 >> bp) & 1)       ? s[j][2] * 0.125f : -1e9f;
            s[j][3] = ((wr1 >> (bp + 1)) & 1) ? s[j][3] * 0.125f : -1e9f;
            mx0 = fmaxf(mx0, fmaxf(s[j][0], s[j][1]));
            mx1 = fmaxf(mx1, fmaxf(s[j][2], s[j][3]));
        }
        mx0 = fmaxf(mx0, __shfl_xor_sync(0xffffffffu, mx0, 1, 4));
        mx0 = fmaxf(mx0, __shfl_xor_sync(0xffffffffu, mx0, 2, 4));
        mx1 = fmaxf(mx1, __shfl_xor_sync(0xffffffffu, mx1, 1, 4));
        mx1 = fmaxf(mx1, __shfl_xor_sync(0xffffffffu, mx1, 2, 4));

        float mn0 = fmaxf(m0r, mx0), mn1 = fmaxf(m1r, mx1);
        float a0 = fast_ex2((m0r - mn0) * LOG2E);
        float a1 = fast_ex2((m1r - mn1) * LOG2E);
        m0r = mn0; m1r = mn1;
        float c0 = -mn0 * LOG2E, c1 = -mn1 * LOG2E;

        float sum0 = 0.0f, sum1 = 0.0f;
        #pragma unroll
        for (int j = 0; j < 8; j++) {
            s[j][0] = fast_ex2(fmaf(s[j][0], LOG2E, c0));
            s[j][1] = fast_ex2(fmaf(s[j][1], LOG2E, c0));
            s[j][2] = fast_ex2(fmaf(s[j][2], LOG2E, c1));
            s[j][3] = fast_ex2(fmaf(s[j][3], LOG2E, c1));
            sum0 += s[j][0] + s[j][1];
            sum1 += s[j][2] + s[j][3];
        }
        sum0 += __shfl_xor_sync(0xffffffffu, sum0, 1, 4);
        sum0 += __shfl_xor_sync(0xffffffffu, sum0, 2, 4);
        sum1 += __shfl_xor_sync(0xffffffffu, sum1, 1, 4);
        sum1 += __shfl_xor_sync(0xffffffffu, sum1, 2, 4);
        l0r = l0r * a0 + sum0;
        l1r = l1r * a1 + sum1;

        #pragma unroll
        for (int j = 0; j < 8; j++) {
            O[j][0] *= a0; O[j][1] *= a0;
            O[j][2] *= a1; O[j][3] *= a1;
        }

        // ---- O += Ph Vh + Pl Vh + Ph Vl ----
        #pragma unroll
        for (int t = 0; t < 4; t++) {
            uint32_t ph[4], pl[4];
            split2(s[2 * t][0],     s[2 * t][1],     ph[0], pl[0]);
            split2(s[2 * t][2],     s[2 * t][3],     ph[1], pl[1]);
            split2(s[2 * t + 1][0], s[2 * t + 1][1], ph[2], pl[2]);
            split2(s[2 * t + 1][2], s[2 * t + 1][3], ph[3], pl[3]);
            const int brow = (lane & 7) + (lane & 8);
            #pragma unroll
            for (int np = 0; np < 4; np++) {
                uint32_t vh[4], vl[4];
                uint32_t va = stg + AT_VH + (uint32_t)(t * 16 + brow) * AT_PITCHB
                            + (uint32_t)(lane & 16) + np * 32;
                ldm_x4_trans(vh, va);
                ldm_x4_trans(vl, va + AT_K2L);
                mma_bf16(O[2 * np],     ph, vh[0], vh[1]);
                mma_bf16(O[2 * np + 1], ph, vh[2], vh[3]);
                mma_bf16(O[2 * np],     pl, vh[0], vh[1]);
                mma_bf16(O[2 * np + 1], pl, vh[2], vh[3]);
                mma_bf16(O[2 * np],     ph, vl[0], vl[1]);
                mma_bf16(O[2 * np + 1], ph, vl[2], vl[3]);
            }
        }
        __syncthreads();
    }

    // ---- epilogue: normalize, write ctx hi/lo bf16 ----
    float inv0 = 1.0f / l0r, inv1 = 1.0f / l1r;
    #pragma unroll
    for (int j = 0; j < 8; j++) {
        int col = h * DK + 8 * j + (lane & 3) * 2;
        size_t r0 = (size_t)(b * S + qg0) * DM + col;
        size_t r1 = (size_t)(b * S + qg0 + 8) * DM + col;
        uint32_t hh, ll;
        split2(O[j][0] * inv0, O[j][1] * inv0, hh, ll);
        *(uint32_t*)&ctxh[r0] = hh;
        *(uint32_t*)&ctxl[r0] = ll;
        split2(O[j][2] * inv1, O[j][3] * inv1, hh, ll);
        *(uint32_t*)&ctxh[r1] = hh;
        *(uint32_t*)&ctxl[r1] = ll;
    }
}

// ---------------------------------------------------------------------------
// Launch
// ---------------------------------------------------------------------------
extern "C" void kernel_launch(void* const* d_in, const int* in_sizes, int n_in,
                              void* d_out, int out_size)
{
    const float* query = (const float*)d_in[0];
    const int*   mask  = (const int*)d_in[1];
    const float* Wqkv  = (const float*)d_in[2];
    const float* bqkv  = (const float*)d_in[3];
    const float* Wout  = (const float*)d_in[4];
    const float* bout  = (const float*)d_in[5];
    float* out = (float*)d_out;

    long long qe = in_sizes[0];
    long long me = in_sizes[1];
    int S = (int)((me * DM) / qe);
    int B = (int)(qe / ((long long)S * DM));
    int M = B * S;

    __nv_bfloat16 *qkvh, *qkvl, *ahi, *alo, *whi, *wlo;
    uint32_t* bm;
    cudaGetSymbolAddress((void**)&qkvh, g_qkvh);
    cudaGetSymbolAddress((void**)&qkvl, g_qkvl);
    cudaGetSymbolAddress((void**)&ahi, g_ahi);
    cudaGetSymbolAddress((void**)&alo, g_alo);
    cudaGetSymbolAddress((void**)&whi, g_whi);
    cudaGetSymbolAddress((void**)&wlo, g_wlo);
    cudaGetSymbolAddress((void**)&bm, g_bm);

    const int GEMM_SMEM = 2 * STAGE_BYTES;
    cudaFuncSetAttribute(gemm_hmma_kernel<0>,
                         cudaFuncAttributeMaxDynamicSharedMemorySize, GEMM_SMEM);
    cudaFuncSetAttribute(gemm_hmma_kernel<1>,
                         cudaFuncAttributeMaxDynamicSharedMemorySize, GEMM_SMEM);
    cudaFuncSetAttribute(attn_mma_kernel,
                         cudaFuncAttributeMaxDynamicSharedMemorySize, AT_SMEM);

    // 1) split W_qkv
    {
        int n4 = (DM * 3 * DM) / 4;
        split_bf16_kernel<<<(n4 + 255) / 256, 256>>>(Wqkv, whi, wlo, n4);
    }
    // 2) split query
    {
        int n4 = (M * DM) / 4;
        split_bf16_kernel<<<(n4 + 255) / 256, 256>>>(query, ahi, alo, n4);
    }
    // 3) mask -> bitmask
    {
        int n = B * S * S;
        mask_bits_kernel<<<(n + 255) / 256, 256>>>(mask, bm, n);
    }
    // 4) QKV GEMM -> bf16 hi/lo
    {
        dim3 grid((3 * DM) / 128, M / 128);
        gemm_hmma_kernel<1><<<grid, 256, GEMM_SMEM>>>(
            ahi, alo, whi, wlo, bqkv, nullptr, qkvh, qkvl, M, 3 * DM, DM);
    }
    // 5) attention -> ctx hi/lo (reuses ahi/alo)
    {
        dim3 grid(S / 128, NH, B);
        attn_mma_kernel<<<grid, 256, AT_SMEM>>>(qkvh, qkvl, bm, ahi, alo, S);
    }
    // 6) split W_out
    {
        int n4 = (DM * DM) / 4;
        split_bf16_kernel<<<(n4 + 255) / 256, 256>>>(Wout, whi, wlo, n4);
    }
    // 7) out GEMM -> fp32
    {
        dim3 grid(DM / 128, M / 128);
        gemm_hmma_kernel<0><<<grid, 256, GEMM_SMEM>>>(
            ahi, alo, whi, wlo, bout, out, nullptr, nullptr, M, DM, DM);
    }
}

// round 5
// speedup vs baseline: 3.1653x; 1.0198x over previous
#include <cuda_runtime.h>
#include <cuda_bf16.h>
#include <cstdint>

#define DM 1024
#define NH 16
#define DK 64
#define LOG2E 1.4426950408889634f

// ---------------------------------------------------------------------------
// Scratch (B=2, S=2048 fixed => M = 4096)
// ---------------------------------------------------------------------------
__device__ __nv_bfloat16 g_qkvh[(size_t)4096 * 3072]; // QKV hi
__device__ __nv_bfloat16 g_qkvl[(size_t)4096 * 3072]; // QKV lo
__device__ __nv_bfloat16 g_ahi[(size_t)4096 * 1024];  // A / ctx hi
__device__ __nv_bfloat16 g_alo[(size_t)4096 * 1024];  // A / ctx lo
__device__ __nv_bfloat16 g_whi[(size_t)1024 * 3072];  // W hi ([K,N] row-major)
__device__ __nv_bfloat16 g_wlo[(size_t)1024 * 3072];  // W lo
__device__ uint32_t g_bm[(size_t)2 * 2048 * 64];      // mask bitmask

__device__ __forceinline__ uint32_t smem_u32(const void* p) {
    uint32_t a;
    asm("{ .reg .u64 t; cvta.to.shared.u64 t, %1; cvt.u32.u64 %0, t; }"
        : "=r"(a) : "l"(p));
    return a;
}
__device__ __forceinline__ void ldm_x4(uint32_t* r, uint32_t addr) {
    asm volatile("ldmatrix.sync.aligned.m8n8.x4.shared.b16 {%0,%1,%2,%3}, [%4];"
                 : "=r"(r[0]), "=r"(r[1]), "=r"(r[2]), "=r"(r[3]) : "r"(addr));
}
__device__ __forceinline__ void ldm_x4_trans(uint32_t* r, uint32_t addr) {
    asm volatile("ldmatrix.sync.aligned.m8n8.x4.trans.shared.b16 {%0,%1,%2,%3}, [%4];"
                 : "=r"(r[0]), "=r"(r[1]), "=r"(r[2]), "=r"(r[3]) : "r"(addr));
}
__device__ __forceinline__ void mma_bf16(float* d, const uint32_t* a,
                                         uint32_t b0, uint32_t b1) {
    asm volatile(
        "mma.sync.aligned.m16n8k16.row.col.f32.bf16.bf16.f32 "
        "{%0,%1,%2,%3}, {%4,%5,%6,%7}, {%8,%9}, {%0,%1,%2,%3};"
        : "+f"(d[0]), "+f"(d[1]), "+f"(d[2]), "+f"(d[3])
        : "r"(a[0]), "r"(a[1]), "r"(a[2]), "r"(a[3]), "r"(b0), "r"(b1));
}
__device__ __forceinline__ float fast_ex2(float x) {
    float y;
    asm("ex2.approx.f32 %0, %1;" : "=f"(y) : "f"(x));
    return y;
}
__device__ __forceinline__ uint32_t pack2(float x, float y) {
    __nv_bfloat162 t = __floats2bfloat162_rn(x, y);
    return *reinterpret_cast<uint32_t*>(&t);
}
__device__ __forceinline__ void split2(float x, float y, uint32_t& hi, uint32_t& lo) {
    __nv_bfloat16 hx = __float2bfloat16(x), hy = __float2bfloat16(y);
    __nv_bfloat162 hp(hx, hy);
    hi = *reinterpret_cast<uint32_t*>(&hp);
    lo = pack2(x - __bfloat162float(hx), y - __bfloat162float(hy));
}
__device__ __forceinline__ void cp16(uint32_t saddr, const void* gaddr) {
    asm volatile("cp.async.cg.shared.global [%0], [%1], 16;" :: "r"(saddr), "l"(gaddr));
}

// ---------------------------------------------------------------------------
// Split fp32 -> bf16 hi/lo
// ---------------------------------------------------------------------------
__global__ __launch_bounds__(256)
void split_bf16_kernel(const float* __restrict__ in, __nv_bfloat16* __restrict__ hi,
                       __nv_bfloat16* __restrict__ lo, int n4)
{
    int i = blockIdx.x * blockDim.x + threadIdx.x;
    if (i >= n4) return;
    float4 v = ((const float4*)in)[i];
    uint32_t h0, l0, h1, l1;
    split2(v.x, v.y, h0, l0);
    split2(v.z, v.w, h1, l1);
    uint2* hp = (uint2*)(hi + 4 * (size_t)i);
    uint2* lp = (uint2*)(lo + 4 * (size_t)i);
    *hp = make_uint2(h0, h1);
    *lp = make_uint2(l0, l1);
}

// ---------------------------------------------------------------------------
// Mask int32 -> bitmask
// ---------------------------------------------------------------------------
__global__ __launch_bounds__(256)
void mask_bits_kernel(const int* __restrict__ mask, uint32_t* __restrict__ bm, int n)
{
    int i = blockIdx.x * blockDim.x + threadIdx.x;
    unsigned bit = (i < n) ? (mask[i] != 0) : 0u;
    unsigned w = __ballot_sync(0xffffffffu, bit);
    if ((i & 31) == 0 && i < n) bm[i >> 5] = w;
}

// ---------------------------------------------------------------------------
// HMMA bf16x3 GEMM, cp.async 2-stage, 2 CTAs/SM.
// OUT=0 -> fp32 C+bias ; OUT=1 -> bf16 hi/lo (bias added)
// ---------------------------------------------------------------------------
#define A_PITCH 40
#define B_PITCH 136
#define OFF_AH 0
#define OFF_AL 10240
#define OFF_BH 20480
#define OFF_BL 29184
#define STAGE_BYTES 37888

template <int OUT>
__global__ __launch_bounds__(256, 2)
void gemm_hmma_kernel(const __nv_bfloat16* __restrict__ Ah,
                      const __nv_bfloat16* __restrict__ Al,
                      const __nv_bfloat16* __restrict__ Wh,
                      const __nv_bfloat16* __restrict__ Wl,
                      const float* __restrict__ bias, float* __restrict__ C,
                      __nv_bfloat16* __restrict__ Ch, __nv_bfloat16* __restrict__ Cl,
                      int M, int N, int K)
{
    extern __shared__ char dsm[];
    const uint32_t sbase = smem_u32(dsm);

    const int tid = threadIdx.x;
    const int lane = tid & 31;
    const int wid = tid >> 5;
    const int wm = (wid & 3) * 32;
    const int wn = (wid >> 2) * 64;
    const int m0 = blockIdx.y * 128;
    const int n0 = blockIdx.x * 128;

    const uint32_t aOff = (uint32_t)(wm + (lane & 15)) * (A_PITCH * 2)
                        + (uint32_t)((lane >> 4) << 4);
    const int brow = (lane & 7) + (lane & 8);
    const uint32_t bOff = (uint32_t)brow * (B_PITCH * 2) + (uint32_t)(lane & 16);

    // per-thread gmem chunk coords (2 chunks each for A and B, hi+lo)
    const int rA0 = tid >> 2, cA0 = (tid & 3) << 3;
    const int rA1 = (tid + 256) >> 2, cA1 = ((tid + 256) & 3) << 3;
    const int rB0 = tid >> 4, cB0 = (tid & 15) << 3;
    const int rB1 = (tid + 256) >> 4, cB1 = ((tid + 256) & 15) << 3;

    auto load_stage = [&](int s, int buf) {
        const uint32_t st = sbase + (uint32_t)buf * STAGE_BYTES;
        const int k0 = s << 5;
        cp16(st + OFF_AH + rA0 * (A_PITCH * 2) + cA0 * 2, Ah + (size_t)(m0 + rA0) * K + k0 + cA0);
        cp16(st + OFF_AL + rA0 * (A_PITCH * 2) + cA0 * 2, Al + (size_t)(m0 + rA0) * K + k0 + cA0);
        cp16(st + OFF_AH + rA1 * (A_PITCH * 2) + cA1 * 2, Ah + (size_t)(m0 + rA1) * K + k0 + cA1);
        cp16(st + OFF_AL + rA1 * (A_PITCH * 2) + cA1 * 2, Al + (size_t)(m0 + rA1) * K + k0 + cA1);
        cp16(st + OFF_BH + rB0 * (B_PITCH * 2) + cB0 * 2, Wh + (size_t)(k0 + rB0) * N + n0 + cB0);
        cp16(st + OFF_BL + rB0 * (B_PITCH * 2) + cB0 * 2, Wl + (size_t)(k0 + rB0) * N + n0 + cB0);
        cp16(st + OFF_BH + rB1 * (B_PITCH * 2) + cB1 * 2, Wh + (size_t)(k0 + rB1) * N + n0 + cB1);
        cp16(st + OFF_BL + rB1 * (B_PITCH * 2) + cB1 * 2, Wl + (size_t)(k0 + rB1) * N + n0 + cB1);
        asm volatile("cp.async.commit_group;");
    };

    float acc[2][8][4];
    #pragma unroll
    for (int mi = 0; mi < 2; mi++)
        #pragma unroll
        for (int nj = 0; nj < 8; nj++)
            #pragma unroll
            for (int q = 0; q < 4; q++) acc[mi][nj][q] = 0.0f;

    const int nStages = K >> 5;
    load_stage(0, 0);

    for (int s = 0; s < nStages; s++) {
        const int buf = s & 1;
        asm volatile("cp.async.wait_group 0;");
        __syncthreads();
        if (s + 1 < nStages) load_stage(s + 1, buf ^ 1);

        const uint32_t sb = sbase + (uint32_t)buf * STAGE_BYTES;
        #pragma unroll
        for (int k16 = 0; k16 < 2; k16++) {
            uint32_t afh[2][4], afl[2][4];
            #pragma unroll
            for (int mi = 0; mi < 2; mi++) {
                uint32_t aa = sb + aOff + (uint32_t)mi * (16 * A_PITCH * 2)
                            + (uint32_t)k16 * 32;
                ldm_x4(afh[mi], aa + OFF_AH);
                ldm_x4(afl[mi], aa + OFF_AL);
            }
            #pragma unroll
            for (int t = 0; t < 4; t++) {
                uint32_t bfh[4], bfl[4];
                uint32_t ba = sb + bOff + (uint32_t)k16 * (16 * B_PITCH * 2)
                            + (uint32_t)(wn + t * 16) * 2;
                ldm_x4_trans(bfh, ba + OFF_BH);
                ldm_x4_trans(bfl, ba + OFF_BL);
                #pragma unroll
                for (int half = 0; half < 2; half++) {
                    int nj = t * 2 + half;
                    uint32_t b0 = bfh[half * 2], b1 = bfh[half * 2 + 1];
                    uint32_t l0 = bfl[half * 2], l1 = bfl[half * 2 + 1];
                    #pragma unroll
                    for (int mi = 0; mi < 2; mi++) {
                        mma_bf16(acc[mi][nj], afh[mi], b0, b1);
                        mma_bf16(acc[mi][nj], afl[mi], b0, b1);
                        mma_bf16(acc[mi][nj], afh[mi], l0, l1);
                    }
                }
            }
        }
        __syncthreads();
    }

    #pragma unroll
    for (int mi = 0; mi < 2; mi++) {
        int r0 = m0 + wm + mi * 16 + (lane >> 2);
        #pragma unroll
        for (int nj = 0; nj < 8; nj++) {
            int c = n0 + wn + nj * 8 + ((lane & 3) << 1);
            float2 bv = *(const float2*)&bias[c];
            float x0 = acc[mi][nj][0] + bv.x, y0 = acc[mi][nj][1] + bv.y;
            float x1 = acc[mi][nj][2] + bv.x, y1 = acc[mi][nj][3] + bv.y;
            if constexpr (OUT == 0) {
                *(float2*)&C[(size_t)r0 * N + c] = make_float2(x0, y0);
                *(float2*)&C[(size_t)(r0 + 8) * N + c] = make_float2(x1, y1);
            } else {
                uint32_t h, l;
                split2(x0, y0, h, l);
                *(uint32_t*)&Ch[(size_t)r0 * N + c] = h;
                *(uint32_t*)&Cl[(size_t)r0 * N + c] = l;
                split2(x1, y1, h, l);
                *(uint32_t*)&Ch[(size_t)(r0 + 8) * N + c] = h;
                *(uint32_t*)&Cl[(size_t)(r0 + 8) * N + c] = l;
            }
        }
    }
}

// ---------------------------------------------------------------------------
// HMMA flash attention (bf16 x3 split), CTA = 128 q-rows, k-tiles of 64.
// ---------------------------------------------------------------------------
#define AT_PITCHB 144
#define AT_QH 0
#define AT_QL 18432
#define AT_STG 36864
#define AT_STGSZ 36864
#define AT_K2L 9216
#define AT_VH 18432
#define AT_SMEM (AT_STG + 2 * AT_STGSZ)

__global__ __launch_bounds__(256, 2)
void attn_mma_kernel(const __nv_bfloat16* __restrict__ qkvh,
                     const __nv_bfloat16* __restrict__ qkvl,
                     const uint32_t* __restrict__ bm,
                     __nv_bfloat16* __restrict__ ctxh,
                     __nv_bfloat16* __restrict__ ctxl, int S)
{
    extern __shared__ char sm[];
    const uint32_t sb = smem_u32(sm);

    const int tid = threadIdx.x;
    const int lane = tid & 31;
    const int w = tid >> 5;
    const int b = blockIdx.z, h = blockIdx.y;
    const int q0 = blockIdx.x * 128;
    const int words = S >> 5;

    // stage loader (K/V hi/lo)
    auto load_stage = [&](int ktIdx, int buf) {
        const uint32_t stg = sb + AT_STG + (uint32_t)buf * AT_STGSZ;
        #pragma unroll
        for (int i = 0; i < 8; i++) {
            int c = tid + 256 * i;
            int arr = c >> 9, row = (c >> 3) & 63, ch = c & 7;
            const __nv_bfloat16* gp = ((arr & 1) ? qkvl : qkvh)
                + (size_t)(b * S + ktIdx * 64 + row) * 3072
                + ((arr >> 1) ? 2048 : 1024) + h * DK + ch * 8;
            cp16(stg + arr * AT_K2L + row * AT_PITCHB + ch * 16, gp);
        }
        asm volatile("cp.async.commit_group;");
    };

    load_stage(0, 0);  // start K/V fetch first

    // Q tile load (hi/lo): 2048 16B chunks
    #pragma unroll
    for (int i = 0; i < 8; i++) {
        int c = tid + 256 * i;
        int arr = c >> 10, row = (c >> 3) & 127, ch = c & 7;
        const __nv_bfloat16* src = (arr ? qkvl : qkvh)
            + (size_t)(b * S + q0 + row) * 3072 + h * DK + ch * 8;
        *(uint4*)(sm + arr * AT_QL + row * AT_PITCHB + ch * 16) = *(const uint4*)src;
    }

    const uint32_t qfoff = (uint32_t)(w * 16 + (lane & 15)) * AT_PITCHB
                         + (uint32_t)((lane >> 4) << 4);
    const int qg0 = q0 + w * 16 + (lane >> 2);
    const size_t bmR0 = (size_t)(b * S + qg0) * words;
    const size_t bmR1 = bmR0 + (size_t)8 * words;

    float O[8][4];
    #pragma unroll
    for (int j = 0; j < 8; j++)
        #pragma unroll
        for (int q = 0; q < 4; q++) O[j][q] = 0.0f;
    float m0r = -1e30f, m1r = -1e30f, l0r = 0.0f, l1r = 0.0f;

    const int nKT = S >> 6;
    for (int kt = 0; kt < nKT; kt++) {
        const int buf = kt & 1;
        const bool hasNext = (kt + 1) < nKT;
        if (hasNext) load_stage(kt + 1, buf ^ 1);
        if (hasNext) asm volatile("cp.async.wait_group 1;");
        else         asm volatile("cp.async.wait_group 0;");
        __syncthreads();

        const uint32_t stg = sb + AT_STG + (uint32_t)buf * AT_STGSZ;

        // ---- S = Qh Kh + Ql Kh + Qh Kl ----
        float s[8][4];
        #pragma unroll
        for (int j = 0; j < 8; j++)
            #pragma unroll
            for (int q = 0; q < 4; q++) s[j][q] = 0.0f;

        #pragma unroll
        for (int t = 0; t < 4; t++) {
            uint32_t qht[4], qlt[4];
            ldm_x4(qht, sb + AT_QH + qfoff + t * 32);
            ldm_x4(qlt, sb + AT_QL + qfoff + t * 32);
            #pragma unroll
            for (int np = 0; np < 4; np++) {
                uint32_t kh[4], kl[4];
                uint32_t ka = stg + (uint32_t)(np * 16 + (lane & 15)) * AT_PITCHB
                            + (uint32_t)((lane >> 4) << 4) + t * 32;
                ldm_x4(kh, ka);
                ldm_x4(kl, ka + AT_K2L);
                mma_bf16(s[2 * np],     qht, kh[0], kh[2]);
                mma_bf16(s[2 * np + 1], qht, kh[1], kh[3]);
                mma_bf16(s[2 * np],     qlt, kh[0], kh[2]);
                mma_bf16(s[2 * np + 1], qlt, kh[1], kh[3]);
                mma_bf16(s[2 * np],     qht, kl[0], kl[2]);
                mma_bf16(s[2 * np + 1], qht, kl[1], kl[3]);
            }
        }

        // ---- mask + online softmax ----
        uint32_t w00 = bm[bmR0 + kt * 2], w01 = bm[bmR0 + kt * 2 + 1];
        uint32_t w10 = bm[bmR1 + kt * 2], w11 = bm[bmR1 + kt * 2 + 1];
        float mx0 = -1e30f, mx1 = -1e30f;
        #pragma unroll
        for (int j = 0; j < 8; j++) {
            uint32_t wr0 = (j < 4) ? w00 : w01;
            uint32_t wr1 = (j < 4) ? w10 : w11;
            int bp = ((j & 3) * 8) + (lane & 3) * 2;
            s[j][0] = ((wr0 >> bp) & 1)       ? s[j][0] * 0.125f : -1e9f;
            s[j][1] = ((wr0 >> (bp + 1)) & 1) ? s[j][1] * 0.125f : -1e9f;
            s[j][2] = ((wr1 >> bp) & 1)       ? s[j][2] * 0.125f : -1e9f;
            s[j][3] = ((wr1 >> (bp + 1)) & 1) ? s[j][3] * 0.125f : -1e9f;
            mx0 = fmaxf(mx0, fmaxf(s[j][0], s[j][1]));
            mx1 = fmaxf(mx1, fmaxf(s[j][2], s[j][3]));
        }
        mx0 = fmaxf(mx0, __shfl_xor_sync(0xffffffffu, mx0, 1, 4));
        mx0 = fmaxf(mx0, __shfl_xor_sync(0xffffffffu, mx0, 2, 4));
        mx1 = fmaxf(mx1, __shfl_xor_sync(0xffffffffu, mx1, 1, 4));
        mx1 = fmaxf(mx1, __shfl_xor_sync(0xffffffffu, mx1, 2, 4));

        float mn0 = fmaxf(m0r, mx0), mn1 = fmaxf(m1r, mx1);
        float a0 = fast_ex2((m0r - mn0) * LOG2E);
        float a1 = fast_ex2((m1r - mn1) * LOG2E);
        m0r = mn0; m1r = mn1;
        float c0 = -mn0 * LOG2E, c1 = -mn1 * LOG2E;

        float sum0 = 0.0f, sum1 = 0.0f;
        #pragma unroll
        for (int j = 0; j < 8; j++) {
            s[j][0] = fast_ex2(fmaf(s[j][0], LOG2E, c0));
            s[j][1] = fast_ex2(fmaf(s[j][1], LOG2E, c0));
            s[j][2] = fast_ex2(fmaf(s[j][2], LOG2E, c1));
            s[j][3] = fast_ex2(fmaf(s[j][3], LOG2E, c1));
            sum0 += s[j][0] + s[j][1];
            sum1 += s[j][2] + s[j][3];
        }
        sum0 += __shfl_xor_sync(0xffffffffu, sum0, 1, 4);
        sum0 += __shfl_xor_sync(0xffffffffu, sum0, 2, 4);
        sum1 += __shfl_xor_sync(0xffffffffu, sum1, 1, 4);
        sum1 += __shfl_xor_sync(0xffffffffu, sum1, 2, 4);
        l0r = l0r * a0 + sum0;
        l1r = l1r * a1 + sum1;

        #pragma unroll
        for (int j = 0; j < 8; j++) {
            O[j][0] *= a0; O[j][1] *= a0;
            O[j][2] *= a1; O[j][3] *= a1;
        }

        // ---- O += Ph Vh + Pl Vh + Ph Vl ----
        #pragma unroll
        for (int t = 0; t < 4; t++) {
            uint32_t ph[4], pl[4];
            split2(s[2 * t][0],     s[2 * t][1],     ph[0], pl[0]);
            split2(s[2 * t][2],     s[2 * t][3],     ph[1], pl[1]);
            split2(s[2 * t + 1][0], s[2 * t + 1][1], ph[2], pl[2]);
            split2(s[2 * t + 1][2], s[2 * t + 1][3], ph[3], pl[3]);
            const int brow = (lane & 7) + (lane & 8);
            #pragma unroll
            for (int np = 0; np < 4; np++) {
                uint32_t vh[4], vl[4];
                uint32_t va = stg + AT_VH + (uint32_t)(t * 16 + brow) * AT_PITCHB
                            + (uint32_t)(lane & 16) + np * 32;
                ldm_x4_trans(vh, va);
                ldm_x4_trans(vl, va + AT_K2L);
                mma_bf16(O[2 * np],     ph, vh[0], vh[1]);
                mma_bf16(O[2 * np + 1], ph, vh[2], vh[3]);
                mma_bf16(O[2 * np],     pl, vh[0], vh[1]);
                mma_bf16(O[2 * np + 1], pl, vh[2], vh[3]);
                mma_bf16(O[2 * np],     ph, vl[0], vl[1]);
                mma_bf16(O[2 * np + 1], ph, vl[2], vl[3]);
            }
        }
        __syncthreads();
    }

    // ---- epilogue: normalize, write ctx hi/lo bf16 ----
    float inv0 = 1.0f / l0r, inv1 = 1.0f / l1r;
    #pragma unroll
    for (int j = 0; j < 8; j++) {
        int col = h * DK + 8 * j + (lane & 3) * 2;
        size_t r0 = (size_t)(b * S + qg0) * DM + col;
        size_t r1 = (size_t)(b * S + qg0 + 8) * DM + col;
        uint32_t hh, ll;
        split2(O[j][0] * inv0, O[j][1] * inv0, hh, ll);
        *(uint32_t*)&ctxh[r0] = hh;
        *(uint32_t*)&ctxl[r0] = ll;
        split2(O[j][2] * inv1, O[j][3] * inv1, hh, ll);
        *(uint32_t*)&ctxh[r1] = hh;
        *(uint32_t*)&ctxl[r1] = ll;
    }
}

// ---------------------------------------------------------------------------
// Launch
// ---------------------------------------------------------------------------
extern "C" void kernel_launch(void* const* d_in, const int* in_sizes, int n_in,
                              void* d_out, int out_size)
{
    const float* query = (const float*)d_in[0];
    const int*   mask  = (const int*)d_in[1];
    const float* Wqkv  = (const float*)d_in[2];
    const float* bqkv  = (const float*)d_in[3];
    const float* Wout  = (const float*)d_in[4];
    const float* bout  = (const float*)d_in[5];
    float* out = (float*)d_out;

    long long qe = in_sizes[0];
    long long me = in_sizes[1];
    int S = (int)((me * DM) / qe);
    int B = (int)(qe / ((long long)S * DM));
    int M = B * S;

    __nv_bfloat16 *qkvh, *qkvl, *ahi, *alo, *whi, *wlo;
    uint32_t* bm;
    cudaGetSymbolAddress((void**)&qkvh, g_qkvh);
    cudaGetSymbolAddress((void**)&qkvl, g_qkvl);
    cudaGetSymbolAddress((void**)&ahi, g_ahi);
    cudaGetSymbolAddress((void**)&alo, g_alo);
    cudaGetSymbolAddress((void**)&whi, g_whi);
    cudaGetSymbolAddress((void**)&wlo, g_wlo);
    cudaGetSymbolAddress((void**)&bm, g_bm);

    const int GEMM_SMEM = 2 * STAGE_BYTES;
    cudaFuncSetAttribute(gemm_hmma_kernel<0>,
                         cudaFuncAttributeMaxDynamicSharedMemorySize, GEMM_SMEM);
    cudaFuncSetAttribute(gemm_hmma_kernel<1>,
                         cudaFuncAttributeMaxDynamicSharedMemorySize, GEMM_SMEM);
    cudaFuncSetAttribute(attn_mma_kernel,
                         cudaFuncAttributeMaxDynamicSharedMemorySize, AT_SMEM);

    // 1) split W_qkv
    {
        int n4 = (DM * 3 * DM) / 4;
        split_bf16_kernel<<<(n4 + 255) / 256, 256>>>(Wqkv, whi, wlo, n4);
    }
    // 2) split query
    {
        int n4 = (M * DM) / 4;
        split_bf16_kernel<<<(n4 + 255) / 256, 256>>>(query, ahi, alo, n4);
    }
    // 3) mask -> bitmask
    {
        int n = B * S * S;
        mask_bits_kernel<<<(n + 255) / 256, 256>>>(mask, bm, n);
    }
    // 4) QKV GEMM -> bf16 hi/lo
    {
        dim3 grid((3 * DM) / 128, M / 128);
        gemm_hmma_kernel<1><<<grid, 256, GEMM_SMEM>>>(
            ahi, alo, whi, wlo, bqkv, nullptr, qkvh, qkvl, M, 3 * DM, DM);
    }
    // 5) attention -> ctx hi/lo (reuses ahi/alo)
    {
        dim3 grid(S / 128, NH, B);
        attn_mma_kernel<<<grid, 256, AT_SMEM>>>(qkvh, qkvl, bm, ahi, alo, S);
    }
    // 6) split W_out
    {
        int n4 = (DM * DM) / 4;
        split_bf16_kernel<<<(n4 + 255) / 256, 256>>>(Wout, whi, wlo, n4);
    }
    // 7) out GEMM -> fp32
    {
        dim3 grid(DM / 128, M / 128);
        gemm_hmma_kernel<0><<<grid, 256, GEMM_SMEM>>>(
            ahi, alo, whi, wlo, bout, out, nullptr, nullptr, M, DM, DM);
    }
}

// round 6
// speedup vs baseline: 3.1688x; 1.0011x over previous
#include <cuda_runtime.h>
#include <cuda_bf16.h>
#include <cstdint>

#define DM 1024
#define NH 16
#define DK 64
#define LOG2E 1.4426950408889634f

// ---------------------------------------------------------------------------
// Scratch (B=2, S=2048 fixed => M = 4096)
// ---------------------------------------------------------------------------
__device__ __nv_bfloat16 g_qkvh[(size_t)4096 * 3072]; // QKV hi
__device__ __nv_bfloat16 g_qkvl[(size_t)4096 * 3072]; // QKV lo
__device__ __nv_bfloat16 g_ahi[(size_t)4096 * 1024];  // A / ctx hi
__device__ __nv_bfloat16 g_alo[(size_t)4096 * 1024];  // A / ctx lo
__device__ __nv_bfloat16 g_whi[(size_t)1024 * 3072];  // W hi ([K,N] row-major)
__device__ __nv_bfloat16 g_wlo[(size_t)1024 * 3072];  // W lo
__device__ uint32_t g_bm[(size_t)2 * 2048 * 64];      // mask bitmask

__device__ __forceinline__ uint32_t smem_u32(const void* p) {
    uint32_t a;
    asm("{ .reg .u64 t; cvta.to.shared.u64 t, %1; cvt.u32.u64 %0, t; }"
        : "=r"(a) : "l"(p));
    return a;
}
__device__ __forceinline__ void ldm_x4(uint32_t* r, uint32_t addr) {
    asm volatile("ldmatrix.sync.aligned.m8n8.x4.shared.b16 {%0,%1,%2,%3}, [%4];"
                 : "=r"(r[0]), "=r"(r[1]), "=r"(r[2]), "=r"(r[3]) : "r"(addr));
}
__device__ __forceinline__ void ldm_x4_trans(uint32_t* r, uint32_t addr) {
    asm volatile("ldmatrix.sync.aligned.m8n8.x4.trans.shared.b16 {%0,%1,%2,%3}, [%4];"
                 : "=r"(r[0]), "=r"(r[1]), "=r"(r[2]), "=r"(r[3]) : "r"(addr));
}
__device__ __forceinline__ void mma_bf16(float* d, const uint32_t* a,
                                         uint32_t b0, uint32_t b1) {
    asm volatile(
        "mma.sync.aligned.m16n8k16.row.col.f32.bf16.bf16.f32 "
        "{%0,%1,%2,%3}, {%4,%5,%6,%7}, {%8,%9}, {%0,%1,%2,%3};"
        : "+f"(d[0]), "+f"(d[1]), "+f"(d[2]), "+f"(d[3])
        : "r"(a[0]), "r"(a[1]), "r"(a[2]), "r"(a[3]), "r"(b0), "r"(b1));
}
__device__ __forceinline__ float fast_ex2(float x) {
    float y;
    asm("ex2.approx.f32 %0, %1;" : "=f"(y) : "f"(x));
    return y;
}
__device__ __forceinline__ uint32_t pack2(float x, float y) {
    __nv_bfloat162 t = __floats2bfloat162_rn(x, y);
    return *reinterpret_cast<uint32_t*>(&t);
}
__device__ __forceinline__ void split2(float x, float y, uint32_t& hi, uint32_t& lo) {
    __nv_bfloat16 hx = __float2bfloat16(x), hy = __float2bfloat16(y);
    __nv_bfloat162 hp(hx, hy);
    hi = *reinterpret_cast<uint32_t*>(&hp);
    lo = pack2(x - __bfloat162float(hx), y - __bfloat162float(hy));
}
__device__ __forceinline__ void cp16(uint32_t saddr, const void* gaddr) {
    asm volatile("cp.async.cg.shared.global [%0], [%1], 16;" :: "r"(saddr), "l"(gaddr));
}

// ---------------------------------------------------------------------------
// Split fp32 -> bf16 hi/lo
// ---------------------------------------------------------------------------
__global__ __launch_bounds__(256)
void split_bf16_kernel(const float* __restrict__ in, __nv_bfloat16* __restrict__ hi,
                       __nv_bfloat16* __restrict__ lo, int n4)
{
    int i = blockIdx.x * blockDim.x + threadIdx.x;
    if (i >= n4) return;
    float4 v = ((const float4*)in)[i];
    uint32_t h0, l0, h1, l1;
    split2(v.x, v.y, h0, l0);
    split2(v.z, v.w, h1, l1);
    uint2* hp = (uint2*)(hi + 4 * (size_t)i);
    uint2* lp = (uint2*)(lo + 4 * (size_t)i);
    *hp = make_uint2(h0, h1);
    *lp = make_uint2(l0, l1);
}

// ---------------------------------------------------------------------------
// Mask int32 -> bitmask
// ---------------------------------------------------------------------------
__global__ __launch_bounds__(256)
void mask_bits_kernel(const int* __restrict__ mask, uint32_t* __restrict__ bm, int n)
{
    int i = blockIdx.x * blockDim.x + threadIdx.x;
    unsigned bit = (i < n) ? (mask[i] != 0) : 0u;
    unsigned w = __ballot_sync(0xffffffffu, bit);
    if ((i & 31) == 0 && i < n) bm[i >> 5] = w;
}

// ---------------------------------------------------------------------------
// HMMA bf16x3 GEMM, cp.async 3-stage ring, ONE sync/stage, 2 CTAs/SM.
// OUT=0 -> fp32 C+bias ; OUT=1 -> bf16 hi/lo (bias added)
// ---------------------------------------------------------------------------
#define A_PITCH 40
#define B_PITCH 136
#define OFF_AH 0
#define OFF_AL 10240
#define OFF_BH 20480
#define OFF_BL 29184
#define STAGE_BYTES 37888
#define NSTG 3

template <int OUT>
__global__ __launch_bounds__(256, 2)
void gemm_hmma_kernel(const __nv_bfloat16* __restrict__ Ah,
                      const __nv_bfloat16* __restrict__ Al,
                      const __nv_bfloat16* __restrict__ Wh,
                      const __nv_bfloat16* __restrict__ Wl,
                      const float* __restrict__ bias, float* __restrict__ C,
                      __nv_bfloat16* __restrict__ Ch, __nv_bfloat16* __restrict__ Cl,
                      int M, int N, int K)
{
    extern __shared__ char dsm[];
    const uint32_t sbase = smem_u32(dsm);

    const int tid = threadIdx.x;
    const int lane = tid & 31;
    const int wid = tid >> 5;
    const int wm = (wid & 3) * 32;
    const int wn = (wid >> 2) * 64;
    const int m0 = blockIdx.y * 128;
    const int n0 = blockIdx.x * 128;

    const uint32_t aOff = (uint32_t)(wm + (lane & 15)) * (A_PITCH * 2)
                        + (uint32_t)((lane >> 4) << 4);
    const int brow = (lane & 7) + (lane & 8);
    const uint32_t bOff = (uint32_t)brow * (B_PITCH * 2) + (uint32_t)(lane & 16);

    // per-thread gmem chunk coords (2 chunks each for A and B, hi+lo)
    const int rA0 = tid >> 2, cA0 = (tid & 3) << 3;
    const int rA1 = (tid + 256) >> 2, cA1 = ((tid + 256) & 3) << 3;
    const int rB0 = tid >> 4, cB0 = (tid & 15) << 3;
    const int rB1 = (tid + 256) >> 4, cB1 = ((tid + 256) & 15) << 3;

    auto load_stage = [&](int s, int buf) {
        const uint32_t st = sbase + (uint32_t)buf * STAGE_BYTES;
        const int k0 = s << 5;
        cp16(st + OFF_AH + rA0 * (A_PITCH * 2) + cA0 * 2, Ah + (size_t)(m0 + rA0) * K + k0 + cA0);
        cp16(st + OFF_AL + rA0 * (A_PITCH * 2) + cA0 * 2, Al + (size_t)(m0 + rA0) * K + k0 + cA0);
        cp16(st + OFF_AH + rA1 * (A_PITCH * 2) + cA1 * 2, Ah + (size_t)(m0 + rA1) * K + k0 + cA1);
        cp16(st + OFF_AL + rA1 * (A_PITCH * 2) + cA1 * 2, Al + (size_t)(m0 + rA1) * K + k0 + cA1);
        cp16(st + OFF_BH + rB0 * (B_PITCH * 2) + cB0 * 2, Wh + (size_t)(k0 + rB0) * N + n0 + cB0);
        cp16(st + OFF_BL + rB0 * (B_PITCH * 2) + cB0 * 2, Wl + (size_t)(k0 + rB0) * N + n0 + cB0);
        cp16(st + OFF_BH + rB1 * (B_PITCH * 2) + cB1 * 2, Wh + (size_t)(k0 + rB1) * N + n0 + cB1);
        cp16(st + OFF_BL + rB1 * (B_PITCH * 2) + cB1 * 2, Wl + (size_t)(k0 + rB1) * N + n0 + cB1);
        asm volatile("cp.async.commit_group;");
    };

    float acc[2][8][4];
    #pragma unroll
    for (int mi = 0; mi < 2; mi++)
        #pragma unroll
        for (int nj = 0; nj < 8; nj++)
            #pragma unroll
            for (int q = 0; q < 4; q++) acc[mi][nj][q] = 0.0f;

    const int nStages = K >> 5;
    load_stage(0, 0);
    load_stage(1, 1);

    int buf = 0, nbuf = 2;
    for (int s = 0; s < nStages; s++) {
        // ensure load(s) complete: outstanding groups are load(s), load(s+1)
        if (s + 1 < nStages) asm volatile("cp.async.wait_group 1;");
        else                 asm volatile("cp.async.wait_group 0;");
        __syncthreads();

        if (s + 2 < nStages) load_stage(s + 2, nbuf);

        const uint32_t sb = sbase + (uint32_t)buf * STAGE_BYTES;
        #pragma unroll
        for (int k16 = 0; k16 < 2; k16++) {
            uint32_t afh[2][4], afl[2][4];
            #pragma unroll
            for (int mi = 0; mi < 2; mi++) {
                uint32_t aa = sb + aOff + (uint32_t)mi * (16 * A_PITCH * 2)
                            + (uint32_t)k16 * 32;
                ldm_x4(afh[mi], aa + OFF_AH);
                ldm_x4(afl[mi], aa + OFF_AL);
            }
            #pragma unroll
            for (int t = 0; t < 4; t++) {
                uint32_t bfh[4], bfl[4];
                uint32_t ba = sb + bOff + (uint32_t)k16 * (16 * B_PITCH * 2)
                            + (uint32_t)(wn + t * 16) * 2;
                ldm_x4_trans(bfh, ba + OFF_BH);
                ldm_x4_trans(bfl, ba + OFF_BL);
                #pragma unroll
                for (int half = 0; half < 2; half++) {
                    int nj = t * 2 + half;
                    uint32_t b0 = bfh[half * 2], b1 = bfh[half * 2 + 1];
                    uint32_t l0 = bfl[half * 2], l1 = bfl[half * 2 + 1];
                    #pragma unroll
                    for (int mi = 0; mi < 2; mi++) {
                        mma_bf16(acc[mi][nj], afh[mi], b0, b1);
                        mma_bf16(acc[mi][nj], afl[mi], b0, b1);
                        mma_bf16(acc[mi][nj], afh[mi], l0, l1);
                    }
                }
            }
        }
        buf = (buf == NSTG - 1) ? 0 : buf + 1;
        nbuf = (nbuf == NSTG - 1) ? 0 : nbuf + 1;
    }

    #pragma unroll
    for (int mi = 0; mi < 2; mi++) {
        int r0 = m0 + wm + mi * 16 + (lane >> 2);
        #pragma unroll
        for (int nj = 0; nj < 8; nj++) {
            int c = n0 + wn + nj * 8 + ((lane & 3) << 1);
            float2 bv = *(const float2*)&bias[c];
            float x0 = acc[mi][nj][0] + bv.x, y0 = acc[mi][nj][1] + bv.y;
            float x1 = acc[mi][nj][2] + bv.x, y1 = acc[mi][nj][3] + bv.y;
            if constexpr (OUT == 0) {
                *(float2*)&C[(size_t)r0 * N + c] = make_float2(x0, y0);
                *(float2*)&C[(size_t)(r0 + 8) * N + c] = make_float2(x1, y1);
            } else {
                uint32_t h, l;
                split2(x0, y0, h, l);
                *(uint32_t*)&Ch[(size_t)r0 * N + c] = h;
                *(uint32_t*)&Cl[(size_t)r0 * N + c] = l;
                split2(x1, y1, h, l);
                *(uint32_t*)&Ch[(size_t)(r0 + 8) * N + c] = h;
                *(uint32_t*)&Cl[(size_t)(r0 + 8) * N + c] = l;
            }
        }
    }
}

// ---------------------------------------------------------------------------
// HMMA flash attention (bf16 x3 split), CTA = 128 q-rows, k-tiles of 64.
// ---------------------------------------------------------------------------
#define AT_PITCHB 144
#define AT_QH 0
#define AT_QL 18432
#define AT_STG 36864
#define AT_STGSZ 36864
#define AT_K2L 9216
#define AT_VH 18432
#define AT_SMEM (AT_STG + 2 * AT_STGSZ)

__global__ __launch_bounds__(256, 2)
void attn_mma_kernel(const __nv_bfloat16* __restrict__ qkvh,
                     const __nv_bfloat16* __restrict__ qkvl,
                     const uint32_t* __restrict__ bm,
                     __nv_bfloat16* __restrict__ ctxh,
                     __nv_bfloat16* __restrict__ ctxl, int S)
{
    extern __shared__ char sm[];
    const uint32_t sb = smem_u32(sm);

    const int tid = threadIdx.x;
    const int lane = tid & 31;
    const int w = tid >> 5;
    const int b = blockIdx.z, h = blockIdx.y;
    const int q0 = blockIdx.x * 128;
    const int words = S >> 5;

    // stage loader (K/V hi/lo)
    auto load_stage = [&](int ktIdx, int buf) {
        const uint32_t stg = sb + AT_STG + (uint32_t)buf * AT_STGSZ;
        #pragma unroll
        for (int i = 0; i < 8; i++) {
            int c = tid + 256 * i;
            int arr = c >> 9, row = (c >> 3) & 63, ch = c & 7;
            const __nv_bfloat16* gp = ((arr & 1) ? qkvl : qkvh)
                + (size_t)(b * S + ktIdx * 64 + row) * 3072
                + ((arr >> 1) ? 2048 : 1024) + h * DK + ch * 8;
            cp16(stg + arr * AT_K2L + row * AT_PITCHB + ch * 16, gp);
        }
        asm volatile("cp.async.commit_group;");
    };

    load_stage(0, 0);  // start K/V fetch first

    // Q tile load (hi/lo): 2048 16B chunks
    #pragma unroll
    for (int i = 0; i < 8; i++) {
        int c = tid + 256 * i;
        int arr = c >> 10, row = (c >> 3) & 127, ch = c & 7;
        const __nv_bfloat16* src = (arr ? qkvl : qkvh)
            + (size_t)(b * S + q0 + row) * 3072 + h * DK + ch * 8;
        *(uint4*)(sm + arr * AT_QL + row * AT_PITCHB + ch * 16) = *(const uint4*)src;
    }

    const uint32_t qfoff = (uint32_t)(w * 16 + (lane & 15)) * AT_PITCHB
                         + (uint32_t)((lane >> 4) << 4);
    const int qg0 = q0 + w * 16 + (lane >> 2);
    const size_t bmR0 = (size_t)(b * S + qg0) * words;
    const size_t bmR1 = bmR0 + (size_t)8 * words;

    float O[8][4];
    #pragma unroll
    for (int j = 0; j < 8; j++)
        #pragma unroll
        for (int q = 0; q < 4; q++) O[j][q] = 0.0f;
    float m0r = -1e30f, m1r = -1e30f, l0r = 0.0f, l1r = 0.0f;

    const int nKT = S >> 6;
    for (int kt = 0; kt < nKT; kt++) {
        const int buf = kt & 1;
        const bool hasNext = (kt + 1) < nKT;

        // prefetch mask words early (hide LDG latency behind MMAs)
        uint32_t w00 = bm[bmR0 + kt * 2], w01 = bm[bmR0 + kt * 2 + 1];
        uint32_t w10 = bm[bmR1 + kt * 2], w11 = bm[bmR1 + kt * 2 + 1];

        if (hasNext) load_stage(kt + 1, buf ^ 1);
        if (hasNext) asm volatile("cp.async.wait_group 1;");
        else         asm volatile("cp.async.wait_group 0;");
        __syncthreads();

        const uint32_t stg = sb + AT_STG + (uint32_t)buf * AT_STGSZ;

        // ---- S = Qh Kh + Ql Kh + Qh Kl ----
        float s[8][4];
        #pragma unroll
        for (int j = 0; j < 8; j++)
            #pragma unroll
            for (int q = 0; q < 4; q++) s[j][q] = 0.0f;

        #pragma unroll
        for (int t = 0; t < 4; t++) {
            uint32_t qht[4], qlt[4];
            ldm_x4(qht, sb + AT_QH + qfoff + t * 32);
            ldm_x4(qlt, sb + AT_QL + qfoff + t * 32);
            #pragma unroll
            for (int np = 0; np < 4; np++) {
                uint32_t kh[4], kl[4];
                uint32_t ka = stg + (uint32_t)(np * 16 + (lane & 15)) * AT_PITCHB
                            + (uint32_t)((lane >> 4) << 4) + t * 32;
                ldm_x4(kh, ka);
                ldm_x4(kl, ka + AT_K2L);
                mma_bf16(s[2 * np],     qht, kh[0], kh[2]);
                mma_bf16(s[2 * np + 1], qht, kh[1], kh[3]);
                mma_bf16(s[2 * np],     qlt, kh[0], kh[2]);
                mma_bf16(s[2 * np + 1], qlt, kh[1], kh[3]);
                mma_bf16(s[2 * np],     qht, kl[0], kl[2]);
                mma_bf16(s[2 * np + 1], qht, kl[1], kl[3]);
            }
        }

        // ---- mask + online softmax ----
        float mx0 = -1e30f, mx1 = -1e30f;
        #pragma unroll
        for (int j = 0; j < 8; j++) {
            uint32_t wr0 = (j < 4) ? w00 : w01;
            uint32_t wr1 = (j < 4) ? w10 : w11;
            int bp = ((j & 3) * 8) + (lane & 3) * 2;
            s[j][0] = ((wr0 >> bp) & 1)       ? s[j][0] * 0.125f : -1e9f;
            s[j][1] = ((wr0 >> (bp + 1)) & 1) ? s[j][1] * 0.125f : -1e9f;
            s[j][2] = ((wr1 >> bp) & 1)       ? s[j][2] * 0.125f : -1e9f;
            s[j][3] = ((wr1 >> (bp + 1)) & 1) ? s[j][3] * 0.125f : -1e9f;
            mx0 = fmaxf(mx0, fmaxf(s[j][0], s[j][1]));
            mx1 = fmaxf(mx1, fmaxf(s[j][2], s[j][3]));
        }
        mx0 = fmaxf(mx0, __shfl_xor_sync(0xffffffffu, mx0, 1, 4));
        mx0 = fmaxf(mx0, __shfl_xor_sync(0xffffffffu, mx0, 2, 4));
        mx1 = fmaxf(mx1, __shfl_xor_sync(0xffffffffu, mx1, 1, 4));
        mx1 = fmaxf(mx1, __shfl_xor_sync(0xffffffffu, mx1, 2, 4));

        float mn0 = fmaxf(m0r, mx0), mn1 = fmaxf(m1r, mx1);
        float a0 = fast_ex2((m0r - mn0) * LOG2E);
        float a1 = fast_ex2((m1r - mn1) * LOG2E);
        m0r = mn0; m1r = mn1;
        float c0 = -mn0 * LOG2E, c1 = -mn1 * LOG2E;

        float sum0 = 0.0f, sum1 = 0.0f;
        #pragma unroll
        for (int j = 0; j < 8; j++) {
            s[j][0] = fast_ex2(fmaf(s[j][0], LOG2E, c0));
            s[j][1] = fast_ex2(fmaf(s[j][1], LOG2E, c0));
            s[j][2] = fast_ex2(fmaf(s[j][2], LOG2E, c1));
            s[j][3] = fast_ex2(fmaf(s[j][3], LOG2E, c1));
            sum0 += s[j][0] + s[j][1];
            sum1 += s[j][2] + s[j][3];
        }
        sum0 += __shfl_xor_sync(0xffffffffu, sum0, 1, 4);
        sum0 += __shfl_xor_sync(0xffffffffu, sum0, 2, 4);
        sum1 += __shfl_xor_sync(0xffffffffu, sum1, 1, 4);
        sum1 += __shfl_xor_sync(0xffffffffu, sum1, 2, 4);
        l0r = l0r * a0 + sum0;
        l1r = l1r * a1 + sum1;

        #pragma unroll
        for (int j = 0; j < 8; j++) {
            O[j][0] *= a0; O[j][1] *= a0;
            O[j][2] *= a1; O[j][3] *= a1;
        }

        // ---- O += Ph Vh + Pl Vh + Ph Vl ----
        #pragma unroll
        for (int t = 0; t < 4; t++) {
            uint32_t ph[4], pl[4];
            split2(s[2 * t][0],     s[2 * t][1],     ph[0], pl[0]);
            split2(s[2 * t][2],     s[2 * t][3],     ph[1], pl[1]);
            split2(s[2 * t + 1][0], s[2 * t + 1][1], ph[2], pl[2]);
            split2(s[2 * t + 1][2], s[2 * t + 1][3], ph[3], pl[3]);
            const int brow = (lane & 7) + (lane & 8);
            #pragma unroll
            for (int np = 0; np < 4; np++) {
                uint32_t vh[4], vl[4];
                uint32_t va = stg + AT_VH + (uint32_t)(t * 16 + brow) * AT_PITCHB
                            + (uint32_t)(lane & 16) + np * 32;
                ldm_x4_trans(vh, va);
                ldm_x4_trans(vl, va + AT_K2L);
                mma_bf16(O[2 * np],     ph, vh[0], vh[1]);
                mma_bf16(O[2 * np + 1], ph, vh[2], vh[3]);
                mma_bf16(O[2 * np],     pl, vh[0], vh[1]);
                mma_bf16(O[2 * np + 1], pl, vh[2], vh[3]);
                mma_bf16(O[2 * np],     ph, vl[0], vl[1]);
                mma_bf16(O[2 * np + 1], ph, vl[2], vl[3]);
            }
        }
        __syncthreads();
    }

    // ---- epilogue: normalize, write ctx hi/lo bf16 ----
    float inv0 = 1.0f / l0r, inv1 = 1.0f / l1r;
    #pragma unroll
    for (int j = 0; j < 8; j++) {
        int col = h * DK + 8 * j + (lane & 3) * 2;
        size_t r0 = (size_t)(b * S + qg0) * DM + col;
        size_t r1 = (size_t)(b * S + qg0 + 8) * DM + col;
        uint32_t hh, ll;
        split2(O[j][0] * inv0, O[j][1] * inv0, hh, ll);
        *(uint32_t*)&ctxh[r0] = hh;
        *(uint32_t*)&ctxl[r0] = ll;
        split2(O[j][2] * inv1, O[j][3] * inv1, hh, ll);
        *(uint32_t*)&ctxh[r1] = hh;
        *(uint32_t*)&ctxl[r1] = ll;
    }
}

// ---------------------------------------------------------------------------
// Launch
// ---------------------------------------------------------------------------
extern "C" void kernel_launch(void* const* d_in, const int* in_sizes, int n_in,
                              void* d_out, int out_size)
{
    const float* query = (const float*)d_in[0];
    const int*   mask  = (const int*)d_in[1];
    const float* Wqkv  = (const float*)d_in[2];
    const float* bqkv  = (const float*)d_in[3];
    const float* Wout  = (const float*)d_in[4];
    const float* bout  = (const float*)d_in[5];
    float* out = (float*)d_out;

    long long qe = in_sizes[0];
    long long me = in_sizes[1];
    int S = (int)((me * DM) / qe);
    int B = (int)(qe / ((long long)S * DM));
    int M = B * S;

    __nv_bfloat16 *qkvh, *qkvl, *ahi, *alo, *whi, *wlo;
    uint32_t* bm;
    cudaGetSymbolAddress((void**)&qkvh, g_qkvh);
    cudaGetSymbolAddress((void**)&qkvl, g_qkvl);
    cudaGetSymbolAddress((void**)&ahi, g_ahi);
    cudaGetSymbolAddress((void**)&alo, g_alo);
    cudaGetSymbolAddress((void**)&whi, g_whi);
    cudaGetSymbolAddress((void**)&wlo, g_wlo);
    cudaGetSymbolAddress((void**)&bm, g_bm);

    const int GEMM_SMEM = NSTG * STAGE_BYTES;
    cudaFuncSetAttribute(gemm_hmma_kernel<0>,
                         cudaFuncAttributeMaxDynamicSharedMemorySize, GEMM_SMEM);
    cudaFuncSetAttribute(gemm_hmma_kernel<1>,
                         cudaFuncAttributeMaxDynamicSharedMemorySize, GEMM_SMEM);
    cudaFuncSetAttribute(attn_mma_kernel,
                         cudaFuncAttributeMaxDynamicSharedMemorySize, AT_SMEM);

    // 1) split W_qkv
    {
        int n4 = (DM * 3 * DM) / 4;
        split_bf16_kernel<<<(n4 + 255) / 256, 256>>>(Wqkv, whi, wlo, n4);
    }
    // 2) split query
    {
        int n4 = (M * DM) / 4;
        split_bf16_kernel<<<(n4 + 255) / 256, 256>>>(query, ahi, alo, n4);
    }
    // 3) mask -> bitmask
    {
        int n = B * S * S;
        mask_bits_kernel<<<(n + 255) / 256, 256>>>(mask, bm, n);
    }
    // 4) QKV GEMM -> bf16 hi/lo
    {
        dim3 grid((3 * DM) / 128, M / 128);
        gemm_hmma_kernel<1><<<grid, 256, GEMM_SMEM>>>(
            ahi, alo, whi, wlo, bqkv, nullptr, qkvh, qkvl, M, 3 * DM, DM);
    }
    // 5) attention -> ctx hi/lo (reuses ahi/alo)
    {
        dim3 grid(S / 128, NH, B);
        attn_mma_kernel<<<grid, 256, AT_SMEM>>>(qkvh, qkvl, bm, ahi, alo, S);
    }
    // 6) split W_out
    {
        int n4 = (DM * DM) / 4;
        split_bf16_kernel<<<(n4 + 255) / 256, 256>>>(Wout, whi, wlo, n4);
    }
    // 7) out GEMM -> fp32
    {
        dim3 grid(DM / 128, M / 128);
        gemm_hmma_kernel<0><<<grid, 256, GEMM_SMEM>>>(
            ahi, alo, whi, wlo, bout, out, nullptr, nullptr, M, DM, DM);
    }
}

// round 7
// speedup vs baseline: 3.1870x; 1.0058x over previous
#include <cuda_runtime.h>
#include <cuda_bf16.h>
#include <cstdint>

#define DM 1024
#define NH 16
#define DK 64
#define LOG2E 1.4426950408889634f

// ---------------------------------------------------------------------------
// Scratch (B=2, S=2048 fixed => M = 4096)
// ---------------------------------------------------------------------------
__device__ __nv_bfloat16 g_qkvh[(size_t)4096 * 3072]; // QKV hi
__device__ __nv_bfloat16 g_qkvl[(size_t)4096 * 3072]; // QKV lo
__device__ __nv_bfloat16 g_ahi[(size_t)4096 * 1024];  // A / ctx hi
__device__ __nv_bfloat16 g_alo[(size_t)4096 * 1024];  // A / ctx lo
__device__ __nv_bfloat16 g_whi[(size_t)1024 * 3072];  // W hi ([K,N] row-major)
__device__ __nv_bfloat16 g_wlo[(size_t)1024 * 3072];  // W lo
__device__ uint32_t g_bm[(size_t)2 * 2048 * 64];      // mask bitmask

__device__ __forceinline__ uint32_t smem_u32(const void* p) {
    uint32_t a;
    asm("{ .reg .u64 t; cvta.to.shared.u64 t, %1; cvt.u32.u64 %0, t; }"
        : "=r"(a) : "l"(p));
    return a;
}
__device__ __forceinline__ void ldm_x4(uint32_t* r, uint32_t addr) {
    asm volatile("ldmatrix.sync.aligned.m8n8.x4.shared.b16 {%0,%1,%2,%3}, [%4];"
                 : "=r"(r[0]), "=r"(r[1]), "=r"(r[2]), "=r"(r[3]) : "r"(addr));
}
__device__ __forceinline__ void ldm_x4_trans(uint32_t* r, uint32_t addr) {
    asm volatile("ldmatrix.sync.aligned.m8n8.x4.trans.shared.b16 {%0,%1,%2,%3}, [%4];"
                 : "=r"(r[0]), "=r"(r[1]), "=r"(r[2]), "=r"(r[3]) : "r"(addr));
}
__device__ __forceinline__ void mma_bf16(float* d, const uint32_t* a,
                                         uint32_t b0, uint32_t b1) {
    asm volatile(
        "mma.sync.aligned.m16n8k16.row.col.f32.bf16.bf16.f32 "
        "{%0,%1,%2,%3}, {%4,%5,%6,%7}, {%8,%9}, {%0,%1,%2,%3};"
        : "+f"(d[0]), "+f"(d[1]), "+f"(d[2]), "+f"(d[3])
        : "r"(a[0]), "r"(a[1]), "r"(a[2]), "r"(a[3]), "r"(b0), "r"(b1));
}
__device__ __forceinline__ float fast_ex2(float x) {
    float y;
    asm("ex2.approx.f32 %0, %1;" : "=f"(y) : "f"(x));
    return y;
}
__device__ __forceinline__ uint32_t pack2(float x, float y) {
    __nv_bfloat162 t = __floats2bfloat162_rn(x, y);
    return *reinterpret_cast<uint32_t*>(&t);
}
__device__ __forceinline__ void split2(float x, float y, uint32_t& hi, uint32_t& lo) {
    __nv_bfloat16 hx = __float2bfloat16(x), hy = __float2bfloat16(y);
    __nv_bfloat162 hp(hx, hy);
    hi = *reinterpret_cast<uint32_t*>(&hp);
    lo = pack2(x - __bfloat162float(hx), y - __bfloat162float(hy));
}
__device__ __forceinline__ void cp16(uint32_t saddr, const void* gaddr) {
    asm volatile("cp.async.cg.shared.global [%0], [%1], 16;" :: "r"(saddr), "l"(gaddr));
}

// ---------------------------------------------------------------------------
// Split fp32 -> bf16 hi/lo
// ---------------------------------------------------------------------------
__global__ __launch_bounds__(256)
void split_bf16_kernel(const float* __restrict__ in, __nv_bfloat16* __restrict__ hi,
                       __nv_bfloat16* __restrict__ lo, int n4)
{
    int i = blockIdx.x * blockDim.x + threadIdx.x;
    if (i >= n4) return;
    float4 v = ((const float4*)in)[i];
    uint32_t h0, l0, h1, l1;
    split2(v.x, v.y, h0, l0);
    split2(v.z, v.w, h1, l1);
    uint2* hp = (uint2*)(hi + 4 * (size_t)i);
    uint2* lp = (uint2*)(lo + 4 * (size_t)i);
    *hp = make_uint2(h0, h1);
    *lp = make_uint2(l0, l1);
}

// ---------------------------------------------------------------------------
// Mask int32 -> bitmask
// ---------------------------------------------------------------------------
__global__ __launch_bounds__(256)
void mask_bits_kernel(const int* __restrict__ mask, uint32_t* __restrict__ bm, int n)
{
    int i = blockIdx.x * blockDim.x + threadIdx.x;
    unsigned bit = (i < n) ? (mask[i] != 0) : 0u;
    unsigned w = __ballot_sync(0xffffffffu, bit);
    if ((i & 31) == 0 && i < n) bm[i >> 5] = w;
}

// ---------------------------------------------------------------------------
// HMMA bf16x3 GEMM, cp.async 3-stage ring (unchanged from round 6)
// ---------------------------------------------------------------------------
#define A_PITCH 40
#define B_PITCH 136
#define OFF_AH 0
#define OFF_AL 10240
#define OFF_BH 20480
#define OFF_BL 29184
#define STAGE_BYTES 37888
#define NSTG 3

template <int OUT>
__global__ __launch_bounds__(256, 2)
void gemm_hmma_kernel(const __nv_bfloat16* __restrict__ Ah,
                      const __nv_bfloat16* __restrict__ Al,
                      const __nv_bfloat16* __restrict__ Wh,
                      const __nv_bfloat16* __restrict__ Wl,
                      const float* __restrict__ bias, float* __restrict__ C,
                      __nv_bfloat16* __restrict__ Ch, __nv_bfloat16* __restrict__ Cl,
                      int M, int N, int K)
{
    extern __shared__ char dsm[];
    const uint32_t sbase = smem_u32(dsm);

    const int tid = threadIdx.x;
    const int lane = tid & 31;
    const int wid = tid >> 5;
    const int wm = (wid & 3) * 32;
    const int wn = (wid >> 2) * 64;
    const int m0 = blockIdx.y * 128;
    const int n0 = blockIdx.x * 128;

    const uint32_t aOff = (uint32_t)(wm + (lane & 15)) * (A_PITCH * 2)
                        + (uint32_t)((lane >> 4) << 4);
    const int brow = (lane & 7) + (lane & 8);
    const uint32_t bOff = (uint32_t)brow * (B_PITCH * 2) + (uint32_t)(lane & 16);

    const int rA0 = tid >> 2, cA0 = (tid & 3) << 3;
    const int rA1 = (tid + 256) >> 2, cA1 = ((tid + 256) & 3) << 3;
    const int rB0 = tid >> 4, cB0 = (tid & 15) << 3;
    const int rB1 = (tid + 256) >> 4, cB1 = ((tid + 256) & 15) << 3;

    auto load_stage = [&](int s, int buf) {
        const uint32_t st = sbase + (uint32_t)buf * STAGE_BYTES;
        const int k0 = s << 5;
        cp16(st + OFF_AH + rA0 * (A_PITCH * 2) + cA0 * 2, Ah + (size_t)(m0 + rA0) * K + k0 + cA0);
        cp16(st + OFF_AL + rA0 * (A_PITCH * 2) + cA0 * 2, Al + (size_t)(m0 + rA0) * K + k0 + cA0);
        cp16(st + OFF_AH + rA1 * (A_PITCH * 2) + cA1 * 2, Ah + (size_t)(m0 + rA1) * K + k0 + cA1);
        cp16(st + OFF_AL + rA1 * (A_PITCH * 2) + cA1 * 2, Al + (size_t)(m0 + rA1) * K + k0 + cA1);
        cp16(st + OFF_BH + rB0 * (B_PITCH * 2) + cB0 * 2, Wh + (size_t)(k0 + rB0) * N + n0 + cB0);
        cp16(st + OFF_BL + rB0 * (B_PITCH * 2) + cB0 * 2, Wl + (size_t)(k0 + rB0) * N + n0 + cB0);
        cp16(st + OFF_BH + rB1 * (B_PITCH * 2) + cB1 * 2, Wh + (size_t)(k0 + rB1) * N + n0 + cB1);
        cp16(st + OFF_BL + rB1 * (B_PITCH * 2) + cB1 * 2, Wl + (size_t)(k0 + rB1) * N + n0 + cB1);
        asm volatile("cp.async.commit_group;");
    };

    float acc[2][8][4];
    #pragma unroll
    for (int mi = 0; mi < 2; mi++)
        #pragma unroll
        for (int nj = 0; nj < 8; nj++)
            #pragma unroll
            for (int q = 0; q < 4; q++) acc[mi][nj][q] = 0.0f;

    const int nStages = K >> 5;
    load_stage(0, 0);
    load_stage(1, 1);

    int buf = 0, nbuf = 2;
    for (int s = 0; s < nStages; s++) {
        if (s + 1 < nStages) asm volatile("cp.async.wait_group 1;");
        else                 asm volatile("cp.async.wait_group 0;");
        __syncthreads();

        if (s + 2 < nStages) load_stage(s + 2, nbuf);

        const uint32_t sb = sbase + (uint32_t)buf * STAGE_BYTES;
        #pragma unroll
        for (int k16 = 0; k16 < 2; k16++) {
            uint32_t afh[2][4], afl[2][4];
            #pragma unroll
            for (int mi = 0; mi < 2; mi++) {
                uint32_t aa = sb + aOff + (uint32_t)mi * (16 * A_PITCH * 2)
                            + (uint32_t)k16 * 32;
                ldm_x4(afh[mi], aa + OFF_AH);
                ldm_x4(afl[mi], aa + OFF_AL);
            }
            #pragma unroll
            for (int t = 0; t < 4; t++) {
                uint32_t bfh[4], bfl[4];
                uint32_t ba = sb + bOff + (uint32_t)k16 * (16 * B_PITCH * 2)
                            + (uint32_t)(wn + t * 16) * 2;
                ldm_x4_trans(bfh, ba + OFF_BH);
                ldm_x4_trans(bfl, ba + OFF_BL);
                #pragma unroll
                for (int half = 0; half < 2; half++) {
                    int nj = t * 2 + half;
                    uint32_t b0 = bfh[half * 2], b1 = bfh[half * 2 + 1];
                    uint32_t l0 = bfl[half * 2], l1 = bfl[half * 2 + 1];
                    #pragma unroll
                    for (int mi = 0; mi < 2; mi++) {
                        mma_bf16(acc[mi][nj], afh[mi], b0, b1);
                        mma_bf16(acc[mi][nj], afl[mi], b0, b1);
                        mma_bf16(acc[mi][nj], afh[mi], l0, l1);
                    }
                }
            }
        }
        buf = (buf == NSTG - 1) ? 0 : buf + 1;
        nbuf = (nbuf == NSTG - 1) ? 0 : nbuf + 1;
    }

    #pragma unroll
    for (int mi = 0; mi < 2; mi++) {
        int r0 = m0 + wm + mi * 16 + (lane >> 2);
        #pragma unroll
        for (int nj = 0; nj < 8; nj++) {
            int c = n0 + wn + nj * 8 + ((lane & 3) << 1);
            float2 bv = *(const float2*)&bias[c];
            float x0 = acc[mi][nj][0] + bv.x, y0 = acc[mi][nj][1] + bv.y;
            float x1 = acc[mi][nj][2] + bv.x, y1 = acc[mi][nj][3] + bv.y;
            if constexpr (OUT == 0) {
                *(float2*)&C[(size_t)r0 * N + c] = make_float2(x0, y0);
                *(float2*)&C[(size_t)(r0 + 8) * N + c] = make_float2(x1, y1);
            } else {
                uint32_t h, l;
                split2(x0, y0, h, l);
                *(uint32_t*)&Ch[(size_t)r0 * N + c] = h;
                *(uint32_t*)&Cl[(size_t)r0 * N + c] = l;
                split2(x1, y1, h, l);
                *(uint32_t*)&Ch[(size_t)(r0 + 8) * N + c] = h;
                *(uint32_t*)&Cl[(size_t)(r0 + 8) * N + c] = l;
            }
        }
    }
}

// ---------------------------------------------------------------------------
// HMMA flash attention v2: 4 warps x 32 q-rows (halves K/V LDSM redundancy).
// CTA = 128 threads, 128 q-rows, k-tiles of 64, 2 CTAs/SM.
// ---------------------------------------------------------------------------
#define AT_PITCHB 144
#define AT_QH 0
#define AT_QL 18432
#define AT_STG 36864
#define AT_STGSZ 36864
#define AT_K2L 9216
#define AT_VH 18432
#define AT_SMEM (AT_STG + 2 * AT_STGSZ)

__global__ __launch_bounds__(128, 2)
void attn_mma_kernel(const __nv_bfloat16* __restrict__ qkvh,
                     const __nv_bfloat16* __restrict__ qkvl,
                     const uint32_t* __restrict__ bm,
                     __nv_bfloat16* __restrict__ ctxh,
                     __nv_bfloat16* __restrict__ ctxl, int S)
{
    extern __shared__ char sm[];
    const uint32_t sb = smem_u32(sm);

    const int tid = threadIdx.x;
    const int lane = tid & 31;
    const int w = tid >> 5;                 // 4 warps
    const int b = blockIdx.z, h = blockIdx.y;
    const int q0 = blockIdx.x * 128;
    const int words = S >> 5;

    // stage loader (K/V hi/lo): 2048 chunks / 128 threads = 16 each
    auto load_stage = [&](int ktIdx, int buf) {
        const uint32_t stg = sb + AT_STG + (uint32_t)buf * AT_STGSZ;
        #pragma unroll
        for (int i = 0; i < 16; i++) {
            int c = tid + 128 * i;
            int arr = c >> 9, row = (c >> 3) & 63, ch = c & 7;
            const __nv_bfloat16* gp = ((arr & 1) ? qkvl : qkvh)
                + (size_t)(b * S + ktIdx * 64 + row) * 3072
                + ((arr >> 1) ? 2048 : 1024) + h * DK + ch * 8;
            cp16(stg + arr * AT_K2L + row * AT_PITCHB + ch * 16, gp);
        }
        asm volatile("cp.async.commit_group;");
    };

    load_stage(0, 0);

    // Q tile load (hi/lo): 2048 chunks / 128 threads = 16 each
    #pragma unroll
    for (int i = 0; i < 16; i++) {
        int c = tid + 128 * i;
        int arr = c >> 10, row = (c >> 3) & 127, ch = c & 7;
        const __nv_bfloat16* src = (arr ? qkvl : qkvh)
            + (size_t)(b * S + q0 + row) * 3072 + h * DK + ch * 8;
        *(uint4*)(sm + arr * AT_QL + row * AT_PITCHB + ch * 16) = *(const uint4*)src;
    }

    // per-warp q-row fragment addressing: warp covers rows w*32 .. w*32+31
    uint32_t qfoff[2];
    #pragma unroll
    for (int mi = 0; mi < 2; mi++)
        qfoff[mi] = (uint32_t)(w * 32 + mi * 16 + (lane & 15)) * AT_PITCHB
                  + (uint32_t)((lane >> 4) << 4);
    const int qg0 = q0 + w * 32 + (lane >> 2);
    // 4 row-streams: k = mi*2 + rg -> row qg0 + mi*16 + rg*8
    size_t bmR[4];
    #pragma unroll
    for (int k = 0; k < 4; k++)
        bmR[k] = (size_t)(b * S + qg0 + 8 * k) * words;  // note: k=mi*2+rg maps to +8*k

    float O[2][8][4];
    #pragma unroll
    for (int mi = 0; mi < 2; mi++)
        #pragma unroll
        for (int j = 0; j < 8; j++)
            #pragma unroll
            for (int q = 0; q < 4; q++) O[mi][j][q] = 0.0f;
    float mr[4] = {-1e30f, -1e30f, -1e30f, -1e30f};
    float lr[4] = {0.0f, 0.0f, 0.0f, 0.0f};

    const int nKT = S >> 6;
    for (int kt = 0; kt < nKT; kt++) {
        const int buf = kt & 1;
        const bool hasNext = (kt + 1) < nKT;

        // prefetch mask words early
        uint32_t mw[4][2];
        #pragma unroll
        for (int k = 0; k < 4; k++) {
            mw[k][0] = bm[bmR[k] + kt * 2];
            mw[k][1] = bm[bmR[k] + kt * 2 + 1];
        }

        if (hasNext) load_stage(kt + 1, buf ^ 1);
        if (hasNext) asm volatile("cp.async.wait_group 1;");
        else         asm volatile("cp.async.wait_group 0;");
        __syncthreads();

        const uint32_t stg = sb + AT_STG + (uint32_t)buf * AT_STGSZ;

        // ---- S = Qh Kh + Ql Kh + Qh Kl ----
        float s[2][8][4];
        #pragma unroll
        for (int mi = 0; mi < 2; mi++)
            #pragma unroll
            for (int j = 0; j < 8; j++)
                #pragma unroll
                for (int q = 0; q < 4; q++) s[mi][j][q] = 0.0f;

        #pragma unroll
        for (int t = 0; t < 4; t++) {
            uint32_t qht[2][4], qlt[2][4];
            #pragma unroll
            for (int mi = 0; mi < 2; mi++) {
                ldm_x4(qht[mi], sb + AT_QH + qfoff[mi] + t * 32);
                ldm_x4(qlt[mi], sb + AT_QL + qfoff[mi] + t * 32);
            }
            #pragma unroll
            for (int np = 0; np < 4; np++) {
                uint32_t kh[4], kl[4];
                uint32_t ka = stg + (uint32_t)(np * 16 + (lane & 15)) * AT_PITCHB
                            + (uint32_t)((lane >> 4) << 4) + t * 32;
                ldm_x4(kh, ka);
                ldm_x4(kl, ka + AT_K2L);
                #pragma unroll
                for (int mi = 0; mi < 2; mi++) {
                    mma_bf16(s[mi][2 * np],     qht[mi], kh[0], kh[2]);
                    mma_bf16(s[mi][2 * np + 1], qht[mi], kh[1], kh[3]);
                    mma_bf16(s[mi][2 * np],     qlt[mi], kh[0], kh[2]);
                    mma_bf16(s[mi][2 * np + 1], qlt[mi], kh[1], kh[3]);
                    mma_bf16(s[mi][2 * np],     qht[mi], kl[0], kl[2]);
                    mma_bf16(s[mi][2 * np + 1], qht[mi], kl[1], kl[3]);
                }
            }
        }

        // ---- mask + online softmax (4 row-streams) ----
        float mx[4] = {-1e30f, -1e30f, -1e30f, -1e30f};
        #pragma unroll
        for (int mi = 0; mi < 2; mi++)
            #pragma unroll
            for (int j = 0; j < 8; j++) {
                int wsel = j >> 2;
                int bp = ((j & 3) * 8) + (lane & 3) * 2;
                uint32_t w0 = mw[mi * 2][wsel], w1 = mw[mi * 2 + 1][wsel];
                s[mi][j][0] = ((w0 >> bp) & 1)       ? s[mi][j][0] * 0.125f : -1e9f;
                s[mi][j][1] = ((w0 >> (bp + 1)) & 1) ? s[mi][j][1] * 0.125f : -1e9f;
                s[mi][j][2] = ((w1 >> bp) & 1)       ? s[mi][j][2] * 0.125f : -1e9f;
                s[mi][j][3] = ((w1 >> (bp + 1)) & 1) ? s[mi][j][3] * 0.125f : -1e9f;
                mx[mi * 2]     = fmaxf(mx[mi * 2],     fmaxf(s[mi][j][0], s[mi][j][1]));
                mx[mi * 2 + 1] = fmaxf(mx[mi * 2 + 1], fmaxf(s[mi][j][2], s[mi][j][3]));
            }
        #pragma unroll
        for (int k = 0; k < 4; k++) {
            mx[k] = fmaxf(mx[k], __shfl_xor_sync(0xffffffffu, mx[k], 1, 4));
            mx[k] = fmaxf(mx[k], __shfl_xor_sync(0xffffffffu, mx[k], 2, 4));
        }

        float aa[4], cc[4];
        #pragma unroll
        for (int k = 0; k < 4; k++) {
            float mn = fmaxf(mr[k], mx[k]);
            aa[k] = fast_ex2((mr[k] - mn) * LOG2E);
            mr[k] = mn;
            cc[k] = -mn * LOG2E;
        }

        float sum[4] = {0.0f, 0.0f, 0.0f, 0.0f};
        #pragma unroll
        for (int mi = 0; mi < 2; mi++)
            #pragma unroll
            for (int j = 0; j < 8; j++) {
                s[mi][j][0] = fast_ex2(fmaf(s[mi][j][0], LOG2E, cc[mi * 2]));
                s[mi][j][1] = fast_ex2(fmaf(s[mi][j][1], LOG2E, cc[mi * 2]));
                s[mi][j][2] = fast_ex2(fmaf(s[mi][j][2], LOG2E, cc[mi * 2 + 1]));
                s[mi][j][3] = fast_ex2(fmaf(s[mi][j][3], LOG2E, cc[mi * 2 + 1]));
                sum[mi * 2]     += s[mi][j][0] + s[mi][j][1];
                sum[mi * 2 + 1] += s[mi][j][2] + s[mi][j][3];
            }
        #pragma unroll
        for (int k = 0; k < 4; k++) {
            sum[k] += __shfl_xor_sync(0xffffffffu, sum[k], 1, 4);
            sum[k] += __shfl_xor_sync(0xffffffffu, sum[k], 2, 4);
            lr[k] = lr[k] * aa[k] + sum[k];
        }

        #pragma unroll
        for (int mi = 0; mi < 2; mi++)
            #pragma unroll
            for (int j = 0; j < 8; j++) {
                O[mi][j][0] *= aa[mi * 2];
                O[mi][j][1] *= aa[mi * 2];
                O[mi][j][2] *= aa[mi * 2 + 1];
                O[mi][j][3] *= aa[mi * 2 + 1];
            }

        // ---- O += Ph Vh + Pl Vh + Ph Vl ----
        const int brow = (lane & 7) + (lane & 8);
        #pragma unroll
        for (int t = 0; t < 4; t++) {
            uint32_t ph[2][4], pl[2][4];
            #pragma unroll
            for (int mi = 0; mi < 2; mi++) {
                split2(s[mi][2 * t][0],     s[mi][2 * t][1],     ph[mi][0], pl[mi][0]);
                split2(s[mi][2 * t][2],     s[mi][2 * t][3],     ph[mi][1], pl[mi][1]);
                split2(s[mi][2 * t + 1][0], s[mi][2 * t + 1][1], ph[mi][2], pl[mi][2]);
                split2(s[mi][2 * t + 1][2], s[mi][2 * t + 1][3], ph[mi][3], pl[mi][3]);
            }
            #pragma unroll
            for (int np = 0; np < 4; np++) {
                uint32_t vh[4], vl[4];
                uint32_t va = stg + AT_VH + (uint32_t)(t * 16 + brow) * AT_PITCHB
                            + (uint32_t)(lane & 16) + np * 32;
                ldm_x4_trans(vh, va);
                ldm_x4_trans(vl, va + AT_K2L);
                #pragma unroll
                for (int mi = 0; mi < 2; mi++) {
                    mma_bf16(O[mi][2 * np],     ph[mi], vh[0], vh[1]);
                    mma_bf16(O[mi][2 * np + 1], ph[mi], vh[2], vh[3]);
                    mma_bf16(O[mi][2 * np],     pl[mi], vh[0], vh[1]);
                    mma_bf16(O[mi][2 * np + 1], pl[mi], vh[2], vh[3]);
                    mma_bf16(O[mi][2 * np],     ph[mi], vl[0], vl[1]);
                    mma_bf16(O[mi][2 * np + 1], ph[mi], vl[2], vl[3]);
                }
            }
        }
        __syncthreads();
    }

    // ---- epilogue: normalize, write ctx hi/lo bf16 ----
    float inv[4];
    #pragma unroll
    for (int k = 0; k < 4; k++) inv[k] = 1.0f / lr[k];
    #pragma unroll
    for (int mi = 0; mi < 2; mi++)
        #pragma unroll
        for (int j = 0; j < 8; j++) {
            int col = h * DK + 8 * j + (lane & 3) * 2;
            size_t r0 = (size_t)(b * S + qg0 + mi * 16) * DM + col;
            size_t r1 = r0 + (size_t)8 * DM;
            uint32_t hh, ll;
            split2(O[mi][j][0] * inv[mi * 2], O[mi][j][1] * inv[mi * 2], hh, ll);
            *(uint32_t*)&ctxh[r0] = hh;
            *(uint32_t*)&ctxl[r0] = ll;
            split2(O[mi][j][2] * inv[mi * 2 + 1], O[mi][j][3] * inv[mi * 2 + 1], hh, ll);
            *(uint32_t*)&ctxh[r1] = hh;
            *(uint32_t*)&ctxl[r1] = ll;
        }
}

// ---------------------------------------------------------------------------
// Launch
// ---------------------------------------------------------------------------
extern "C" void kernel_launch(void* const* d_in, const int* in_sizes, int n_in,
                              void* d_out, int out_size)
{
    const float* query = (const float*)d_in[0];
    const int*   mask  = (const int*)d_in[1];
    const float* Wqkv  = (const float*)d_in[2];
    const float* bqkv  = (const float*)d_in[3];
    const float* Wout  = (const float*)d_in[4];
    const float* bout  = (const float*)d_in[5];
    float* out = (float*)d_out;

    long long qe = in_sizes[0];
    long long me = in_sizes[1];
    int S = (int)((me * DM) / qe);
    int B = (int)(qe / ((long long)S * DM));
    int M = B * S;

    __nv_bfloat16 *qkvh, *qkvl, *ahi, *alo, *whi, *wlo;
    uint32_t* bm;
    cudaGetSymbolAddress((void**)&qkvh, g_qkvh);
    cudaGetSymbolAddress((void**)&qkvl, g_qkvl);
    cudaGetSymbolAddress((void**)&ahi, g_ahi);
    cudaGetSymbolAddress((void**)&alo, g_alo);
    cudaGetSymbolAddress((void**)&whi, g_whi);
    cudaGetSymbolAddress((void**)&wlo, g_wlo);
    cudaGetSymbolAddress((void**)&bm, g_bm);

    const int GEMM_SMEM = NSTG * STAGE_BYTES;
    cudaFuncSetAttribute(gemm_hmma_kernel<0>,
                         cudaFuncAttributeMaxDynamicSharedMemorySize, GEMM_SMEM);
    cudaFuncSetAttribute(gemm_hmma_kernel<1>,
                         cudaFuncAttributeMaxDynamicSharedMemorySize, GEMM_SMEM);
    cudaFuncSetAttribute(attn_mma_kernel,
                         cudaFuncAttributeMaxDynamicSharedMemorySize, AT_SMEM);

    // 1) split W_qkv
    {
        int n4 = (DM * 3 * DM) / 4;
        split_bf16_kernel<<<(n4 + 255) / 256, 256>>>(Wqkv, whi, wlo, n4);
    }
    // 2) split query
    {
        int n4 = (M * DM) / 4;
        split_bf16_kernel<<<(n4 + 255) / 256, 256>>>(query, ahi, alo, n4);
    }
    // 3) mask -> bitmask
    {
        int n = B * S * S;
        mask_bits_kernel<<<(n + 255) / 256, 256>>>(mask, bm, n);
    }
    // 4) QKV GEMM -> bf16 hi/lo
    {
        dim3 grid((3 * DM) / 128, M / 128);
        gemm_hmma_kernel<1><<<grid, 256, GEMM_SMEM>>>(
            ahi, alo, whi, wlo, bqkv, nullptr, qkvh, qkvl, M, 3 * DM, DM);
    }
    // 5) attention -> ctx hi/lo (reuses ahi/alo)
    {
        dim3 grid(S / 128, NH, B);
        attn_mma_kernel<<<grid, 128, AT_SMEM>>>(qkvh, qkvl, bm, ahi, alo, S);
    }
    // 6) split W_out
    {
        int n4 = (DM * DM) / 4;
        split_bf16_kernel<<<(n4 + 255) / 256, 256>>>(Wout, whi, wlo, n4);
    }
    // 7) out GEMM -> fp32
    {
        dim3 grid(DM / 128, M / 128);
        gemm_hmma_kernel<0><<<grid, 256, GEMM_SMEM>>>(
            ahi, alo, whi, wlo, bout, out, nullptr, nullptr, M, DM, DM);
    }
}